// round 11
// baseline (speedup 1.0000x reference)
#include <cuda_runtime.h>
#include <cstdint>
#include <math.h>

// Problem constants
constexpr int B_  = 2;
constexpr int L_  = 2048;
constexpr int D_  = 1024;
constexpr int NH  = 16;
constexpr int HD  = 64;
constexpr int M_  = B_ * L_;     // 4096 rows for projections

// Scratch (device globals; no allocation allowed)
__device__ float  g_Qp[B_ * NH * L_ * HD];   // (b, n, l, h) roped, tf32-truncated
__device__ float  g_Kp[B_ * NH * L_ * HD];   // (b, n, l, h) roped, tf32-truncated
__device__ float  g_Vp[B_ * NH * L_ * HD];   // (b, n, l, h), tf32-truncated
__device__ float  g_Ctx[B_ * L_ * D_];       // attention output, tf32-truncated
__device__ float2 g_rope[L_ * (HD / 2)];     // (cos, sin) per (l, i)
// tf32-truncated copies of inputs/weights (prepass output)
__device__ float  g_qT[M_ * D_];
__device__ float  g_kT[M_ * D_];
__device__ float  g_vT[M_ * D_];
__device__ float  g_WT[4 * D_ * D_];         // Wq, Wk, Wv, Wo

// ---------------------------------------------------------------------------
// PTX helpers (mma.sync / ldmatrix / cp.async — all valid at target sm_103)
// ---------------------------------------------------------------------------
__device__ __forceinline__ uint32_t smem_u32(const void* p) {
    uint32_t a;
    asm("{ .reg .u64 t; cvta.to.shared.u64 t, %1; cvt.u32.u64 %0, t; }" : "=r"(a) : "l"(p));
    return a;
}

__device__ __forceinline__ void cp_async16(uint32_t saddr, const void* gaddr) {
    asm volatile("cp.async.cg.shared.global [%0], [%1], 16;" :: "r"(saddr), "l"(gaddr) : "memory");
}
__device__ __forceinline__ void cp_commit() {
    asm volatile("cp.async.commit_group;" ::: "memory");
}
template<int N> __device__ __forceinline__ void cp_wait() {
    asm volatile("cp.async.wait_group %0;" :: "n"(N) : "memory");
}

__device__ __forceinline__ void ldsm4(uint32_t& r0, uint32_t& r1, uint32_t& r2, uint32_t& r3,
                                      uint32_t addr) {
    asm volatile("ldmatrix.sync.aligned.m8n8.x4.shared.b16 {%0,%1,%2,%3}, [%4];"
                 : "=r"(r0), "=r"(r1), "=r"(r2), "=r"(r3) : "r"(addr));
}

__device__ __forceinline__ float cvt_tf32f(float x) {
    uint32_t r = __float_as_uint(x);
    asm("cvt.rna.tf32.f32 %0, %0;" : "+r"(r));
    return __uint_as_float(r);
}

__device__ __forceinline__ void mma_tf32(float* c, const uint32_t* a, const uint32_t* b) {
    asm volatile(
        "mma.sync.aligned.m16n8k8.row.col.f32.tf32.tf32.f32 "
        "{%0,%1,%2,%3}, {%4,%5,%6,%7}, {%8,%9}, {%0,%1,%2,%3};"
        : "+f"(c[0]), "+f"(c[1]), "+f"(c[2]), "+f"(c[3])
        : "r"(a[0]), "r"(a[1]), "r"(a[2]), "r"(a[3]), "r"(b[0]), "r"(b[1]));
}

// ---------------------------------------------------------------------------
// Prepass: rna-truncate to tf32 (so mainloops can skip cvt entirely)
// ---------------------------------------------------------------------------
__global__ void trunc_kernel(const float4* __restrict__ src, float4* __restrict__ dst, int n4) {
    int i = blockIdx.x * blockDim.x + threadIdx.x;
    if (i >= n4) return;
    float4 v = src[i];
    v.x = cvt_tf32f(v.x); v.y = cvt_tf32f(v.y);
    v.z = cvt_tf32f(v.z); v.w = cvt_tf32f(v.w);
    dst[i] = v;
}

// ---------------------------------------------------------------------------
// RoPE table
// ---------------------------------------------------------------------------
__global__ void rope_table_kernel() {
    int idx = blockIdx.x * blockDim.x + threadIdx.x;
    if (idx >= L_ * (HD / 2)) return;
    int l = idx >> 5;
    int i = idx & 31;
    float inv = powf(10000.0f, -(float)(2 * i) / 64.0f);
    float ang = (float)l * inv;
    float s, c;
    sincosf(ang, &s, &c);
    g_rope[idx] = make_float2(c, s);
}

// ---------------------------------------------------------------------------
// tf32 mma.sync GEMM core — cvt-free (inputs pre-truncated)
// ---------------------------------------------------------------------------
constexpr int P_ = 36;                          // smem pitch (floats)
constexpr int TILE_BYTES  = 128 * P_ * 4;       // 18432
constexpr int STAGE_BYTES = 2 * TILE_BYTES;     // X + W
constexpr int GEMM_SMEM   = 2 * STAGE_BYTES;    // 73728

__device__ __forceinline__ void mma_proj_core(
    const float* __restrict__ X, const float* __restrict__ W,
    uint32_t sb, int m0, int n0, float acc[2][8][4])
{
    int tid = threadIdx.x;

    #pragma unroll
    for (int mf = 0; mf < 2; mf++)
        #pragma unroll
        for (int nf = 0; nf < 8; nf++)
            #pragma unroll
            for (int r = 0; r < 4; r++) acc[mf][nf][r] = 0.0f;

    const int lrow = tid >> 3;
    const int lcol = (tid & 7) * 4;
    const float* Xg = X + (size_t)(m0 + lrow) * D_ + lcol;
    const float* Wg = W + (size_t)(n0 + lrow) * D_ + lcol;
    const uint32_t sX = sb + (lrow * P_ + lcol) * 4;
    const uint32_t sW = sX + TILE_BYTES;

    const int lane = tid & 31;
    const int wm = (tid >> 5) & 3;
    const int wn = tid >> 7;
    const int arow = lane & 15;
    const int acol = (lane >> 4) * 4;
    const int brow = lane & 7;
    const int bcol = ((lane >> 3) & 1) * 4;
    const int bhi  = (lane >> 4) * 8;

    #pragma unroll
    for (int i = 0; i < 4; i++) {
        cp_async16(sX + i * 32 * P_ * 4, Xg + (size_t)i * 32 * D_);
        cp_async16(sW + i * 32 * P_ * 4, Wg + (size_t)i * 32 * D_);
    }
    cp_commit();

    for (int it = 0; it < 32; it++) {
        int s = it & 1;
        if (it < 31) {
            uint32_t off = ((it + 1) & 1) * STAGE_BYTES;
            int k0 = (it + 1) * 32;
            #pragma unroll
            for (int i = 0; i < 4; i++) {
                cp_async16(sX + off + i * 32 * P_ * 4, Xg + k0 + (size_t)i * 32 * D_);
                cp_async16(sW + off + i * 32 * P_ * 4, Wg + k0 + (size_t)i * 32 * D_);
            }
            cp_commit();
            cp_wait<1>();
        } else {
            cp_wait<0>();
        }
        __syncthreads();

        uint32_t xb = sb + s * STAGE_BYTES;
        uint32_t wb = xb + TILE_BYTES;

        #pragma unroll
        for (int ks = 0; ks < 4; ks++) {
            int kc = ks * 8;
            uint32_t a[2][4];
            #pragma unroll
            for (int mf = 0; mf < 2; mf++) {
                uint32_t addr = xb + ((wm * 32 + mf * 16 + arow) * P_ + kc + acol) * 4;
                ldsm4(a[mf][0], a[mf][1], a[mf][2], a[mf][3], addr);
            }
            uint32_t b[8][2];
            #pragma unroll
            for (int nf2 = 0; nf2 < 4; nf2++) {
                uint32_t addr = wb + ((wn * 64 + nf2 * 16 + bhi + brow) * P_ + kc + bcol) * 4;
                uint32_t r0, r1, r2, r3;
                ldsm4(r0, r1, r2, r3, addr);
                b[nf2 * 2][0] = r0; b[nf2 * 2][1] = r1;
                b[nf2 * 2 + 1][0] = r2; b[nf2 * 2 + 1][1] = r3;
            }
            #pragma unroll
            for (int mf = 0; mf < 2; mf++)
                #pragma unroll
                for (int nf = 0; nf < 8; nf++)
                    mma_tf32(acc[mf][nf], a[mf], b[nf]);
        }
        __syncthreads();
    }
}

// ---------------------------------------------------------------------------
// QKV projection: bias + RoPE (z<2) + tf32-truncate + scatter to (b,n,l,h)
// ---------------------------------------------------------------------------
__global__ __launch_bounds__(256, 2) void mma_qkv_kernel(
    const float* __restrict__ bq, const float* __restrict__ bk, const float* __restrict__ bv)
{
    extern __shared__ float sm[];
    uint32_t sb = smem_u32(sm);

    int z = blockIdx.z;
    const float* X    = (z == 0) ? g_qT : (z == 1) ? g_kT : g_vT;
    const float* W    = g_WT + (size_t)z * D_ * D_;
    const float* bias = (z == 0) ? bq : (z == 1) ? bk : bv;
    float* dstb       = (z == 0) ? g_Qp : (z == 1) ? g_Kp : g_Vp;
    bool do_rope = (z < 2);

    int m0 = blockIdx.y * 128;
    int n0 = blockIdx.x * 128;

    float acc[2][8][4];
    mma_proj_core(X, W, sb, m0, n0, acc);

    int tid = threadIdx.x;
    int lane = tid & 31;
    int wm = (tid >> 5) & 3;
    int wn = tid >> 7;
    int g = lane >> 2, tq = lane & 3;

    #pragma unroll
    for (int mf = 0; mf < 2; mf++) {
        #pragma unroll
        for (int rr = 0; rr < 2; rr++) {
            int m = m0 + wm * 32 + mf * 16 + g + rr * 8;
            int l = m & (L_ - 1);
            int bb = m >> 11;
            #pragma unroll
            for (int nf = 0; nf < 8; nf++) {
                int col = n0 + wn * 64 + nf * 8 + tq * 2;
                float2 b2 = *(const float2*)&bias[col];
                float c0 = acc[mf][nf][rr * 2 + 0] + b2.x;
                float c1 = acc[mf][nf][rr * 2 + 1] + b2.y;
                int h = col & 63;
                if (do_rope) {
                    float2 cs = g_rope[(l << 5) + (h >> 1)];
                    float e = c0, o = c1;
                    c0 = e * cs.x - o * cs.y;
                    c1 = o * cs.x + e * cs.y;
                }
                int n = col >> 6;
                float* dst = dstb + (((size_t)(bb * NH + n)) * L_ + l) * HD + h;
                *(float2*)dst = make_float2(cvt_tf32f(c0), cvt_tf32f(c1));
            }
        }
    }
}

// ---------------------------------------------------------------------------
// Output projection: Y = g_Ctx @ Wo^T + bo (full fp32 output)
// ---------------------------------------------------------------------------
__global__ __launch_bounds__(256, 2) void mma_out_kernel(
    const float* __restrict__ bo, float* __restrict__ Y)
{
    extern __shared__ float sm[];
    uint32_t sb = smem_u32(sm);

    int m0 = blockIdx.y * 128;
    int n0 = blockIdx.x * 128;

    float acc[2][8][4];
    mma_proj_core(g_Ctx, g_WT + (size_t)3 * D_ * D_, sb, m0, n0, acc);

    int tid = threadIdx.x;
    int lane = tid & 31;
    int wm = (tid >> 5) & 3;
    int wn = tid >> 7;
    int g = lane >> 2, tq = lane & 3;

    #pragma unroll
    for (int mf = 0; mf < 2; mf++) {
        #pragma unroll
        for (int rr = 0; rr < 2; rr++) {
            int m = m0 + wm * 32 + mf * 16 + g + rr * 8;
            #pragma unroll
            for (int nf = 0; nf < 8; nf++) {
                int col = n0 + wn * 64 + nf * 8 + tq * 2;
                float2 b2 = *(const float2*)&bo[col];
                *(float2*)&Y[(size_t)m * D_ + col] =
                    make_float2(acc[mf][nf][rr * 2 + 0] + b2.x,
                                acc[mf][nf][rr * 2 + 1] + b2.y);
            }
        }
    }
}

// ---------------------------------------------------------------------------
// Flash attention via tf32 mma.sync — cvt-free mainloop (Q/K/V pre-truncated;
// P truncated at store). Grid (L/64, B*NH), 128 threads = 4 warps.
// ---------------------------------------------------------------------------
constexpr int AAP = 68;
constexpr int ATT_SMEM = (3 * 64 * AAP) * 4 + 64 * 4;  // Ks, Vt, Ps + mask
constexpr float SCALE_ = 0.03125f;                     // 1/sqrt(1024)

__global__ __launch_bounds__(128) void attn_mma_kernel(const unsigned int* __restrict__ maskw)
{
    extern __shared__ float smf[];
    float* Ks = smf;                  // [64][AAP] row = token, col = hd
    float* Vt = Ks + 64 * AAP;        // [64][AAP] row = hd,   col = token
    float* Ps = Vt + 64 * AAP;        // [64][AAP] row = q-row, col = token (also Q staging)
    unsigned int* msk = (unsigned int*)(Ps + 64 * AAP);

    const uint32_t sKs = smem_u32(Ks);
    const uint32_t sVt = smem_u32(Vt);
    const uint32_t sPs = smem_u32(Ps);

    int bh = blockIdx.y;
    int q0 = blockIdx.x * 64;
    int b  = bh >> 4;
    int n  = bh & 15;

    const float* Q = g_Qp + (size_t)bh * L_ * HD;
    const float* K = g_Kp + (size_t)bh * L_ * HD;
    const float* V = g_Vp + (size_t)bh * L_ * HD;

    int tid  = threadIdx.x;
    int lane = tid & 31;
    int w    = tid >> 5;              // warp 0..3
    int g    = lane >> 2, tq = lane & 3;
    int arow = lane & 15;
    int acol = (lane >> 4) * 4;
    int brow = lane & 7;
    int bcol = ((lane >> 3) & 1) * 4;
    int bhi  = (lane >> 4) * 8;

    // ---- stage Q into Ps, preload A-frags (already tf32-truncated) ----
    #pragma unroll
    for (int idx = tid; idx < 64 * 16; idx += 128) {
        int r = idx >> 4, c4 = (idx & 15) * 4;
        *(float4*)&Ps[r * AAP + c4] = *(const float4*)&Q[(size_t)(q0 + r) * HD + c4];
    }
    __syncthreads();

    uint32_t aq[8][4];
    #pragma unroll
    for (int ks = 0; ks < 8; ks++) {
        uint32_t addr = sPs + ((w * 16 + arow) * AAP + ks * 8 + acol) * 4;
        ldsm4(aq[ks][0], aq[ks][1], aq[ks][2], aq[ks][3], addr);
    }
    __syncthreads();

    float m_0 = -INFINITY, m_1 = -INFINITY, l_0 = 0.0f, l_1 = 0.0f;
    float o[8][4];
    #pragma unroll
    for (int nf = 0; nf < 8; nf++)
        #pragma unroll
        for (int r = 0; r < 4; r++) o[nf][r] = 0.0f;

    for (int kt = 0; kt < L_ / 64; kt++) {
        int k0 = kt * 64;
        __syncthreads();      // previous tile fully consumed

        // K tile (64x64), direct
        #pragma unroll
        for (int idx = tid; idx < 64 * 16; idx += 128) {
            int r = idx >> 4, c4 = (idx & 15) * 4;
            *(float4*)&Ks[r * AAP + c4] = *(const float4*)&K[(size_t)(k0 + r) * HD + c4];
        }
        // V tile transposed: 4x4 register blocks, 2 blocks per thread
        #pragma unroll
        for (int i = 0; i < 2; i++) {
            int bl = tid + i * 128;
            int tb = bl >> 4;     // token block
            int hb = bl & 15;     // hd block
            float4 r0 = *(const float4*)&V[(size_t)(k0 + tb * 4 + 0) * HD + hb * 4];
            float4 r1 = *(const float4*)&V[(size_t)(k0 + tb * 4 + 1) * HD + hb * 4];
            float4 r2 = *(const float4*)&V[(size_t)(k0 + tb * 4 + 2) * HD + hb * 4];
            float4 r3 = *(const float4*)&V[(size_t)(k0 + tb * 4 + 3) * HD + hb * 4];
            *(float4*)&Vt[(hb * 4 + 0) * AAP + tb * 4] = make_float4(r0.x, r1.x, r2.x, r3.x);
            *(float4*)&Vt[(hb * 4 + 1) * AAP + tb * 4] = make_float4(r0.y, r1.y, r2.y, r3.y);
            *(float4*)&Vt[(hb * 4 + 2) * AAP + tb * 4] = make_float4(r0.z, r1.z, r2.z, r3.z);
            *(float4*)&Vt[(hb * 4 + 3) * AAP + tb * 4] = make_float4(r0.w, r1.w, r2.w, r3.w);
        }
        if (tid < 64) msk[tid] = maskw[b * L_ + k0 + tid];
        __syncthreads();

        // ---- S = Q @ K^T ----
        float sc[8][4];
        #pragma unroll
        for (int nf = 0; nf < 8; nf++)
            #pragma unroll
            for (int r = 0; r < 4; r++) sc[nf][r] = 0.0f;

        #pragma unroll
        for (int ks = 0; ks < 8; ks++) {
            int kc = ks * 8;
            uint32_t bfr[8][2];
            #pragma unroll
            for (int nf2 = 0; nf2 < 4; nf2++) {
                uint32_t addr = sKs + ((nf2 * 16 + bhi + brow) * AAP + kc + bcol) * 4;
                uint32_t r0, r1, r2, r3;
                ldsm4(r0, r1, r2, r3, addr);
                bfr[nf2 * 2][0] = r0; bfr[nf2 * 2][1] = r1;
                bfr[nf2 * 2 + 1][0] = r2; bfr[nf2 * 2 + 1][1] = r3;
            }
            #pragma unroll
            for (int nf = 0; nf < 8; nf++)
                mma_tf32(sc[nf], aq[ks], bfr[nf]);
        }

        // ---- online softmax (rows g, g+8 of warp tile) ----
        float mx0 = -INFINITY, mx1 = -INFINITY;
        #pragma unroll
        for (int nf = 0; nf < 8; nf++) {
            int c0 = nf * 8 + tq * 2;
            bool k0m = msk[c0] != 0;
            bool k1m = msk[c0 + 1] != 0;
            sc[nf][0] = k0m ? -1e8f : sc[nf][0] * SCALE_;
            sc[nf][1] = k1m ? -1e8f : sc[nf][1] * SCALE_;
            sc[nf][2] = k0m ? -1e8f : sc[nf][2] * SCALE_;
            sc[nf][3] = k1m ? -1e8f : sc[nf][3] * SCALE_;
            mx0 = fmaxf(mx0, fmaxf(sc[nf][0], sc[nf][1]));
            mx1 = fmaxf(mx1, fmaxf(sc[nf][2], sc[nf][3]));
        }
        mx0 = fmaxf(mx0, __shfl_xor_sync(0xffffffffu, mx0, 1));
        mx0 = fmaxf(mx0, __shfl_xor_sync(0xffffffffu, mx0, 2));
        mx1 = fmaxf(mx1, __shfl_xor_sync(0xffffffffu, mx1, 1));
        mx1 = fmaxf(mx1, __shfl_xor_sync(0xffffffffu, mx1, 2));

        float mn0 = fmaxf(m_0, mx0);
        float mn1 = fmaxf(m_1, mx1);
        float sc0 = __expf(m_0 - mn0);
        float sc1 = __expf(m_1 - mn1);

        float ll0 = 0.0f, ll1 = 0.0f;
        #pragma unroll
        for (int nf = 0; nf < 8; nf++) {
            float p0 = __expf(sc[nf][0] - mn0);
            float p1 = __expf(sc[nf][1] - mn0);
            float p2 = __expf(sc[nf][2] - mn1);
            float p3 = __expf(sc[nf][3] - mn1);
            ll0 += p0 + p1;
            ll1 += p2 + p3;
            int c0 = nf * 8 + tq * 2;
            *(float2*)&Ps[(w * 16 + g) * AAP + c0]     = make_float2(cvt_tf32f(p0), cvt_tf32f(p1));
            *(float2*)&Ps[(w * 16 + g + 8) * AAP + c0] = make_float2(cvt_tf32f(p2), cvt_tf32f(p3));
        }
        ll0 += __shfl_xor_sync(0xffffffffu, ll0, 1);
        ll0 += __shfl_xor_sync(0xffffffffu, ll0, 2);
        ll1 += __shfl_xor_sync(0xffffffffu, ll1, 1);
        ll1 += __shfl_xor_sync(0xffffffffu, ll1, 2);

        l_0 = l_0 * sc0 + ll0;
        l_1 = l_1 * sc1 + ll1;
        m_0 = mn0;
        m_1 = mn1;

        #pragma unroll
        for (int nf = 0; nf < 8; nf++) {
            o[nf][0] *= sc0; o[nf][1] *= sc0;
            o[nf][2] *= sc1; o[nf][3] *= sc1;
        }
        __syncwarp();     // Ps rows are warp-private

        // ---- O += P @ V ----
        #pragma unroll
        for (int ks = 0; ks < 8; ks++) {
            int kc = ks * 8;
            uint32_t ap[4];
            {
                uint32_t addr = sPs + ((w * 16 + arow) * AAP + kc + acol) * 4;
                ldsm4(ap[0], ap[1], ap[2], ap[3], addr);
            }
            uint32_t bfr[8][2];
            #pragma unroll
            for (int nf2 = 0; nf2 < 4; nf2++) {
                uint32_t addr = sVt + ((nf2 * 16 + bhi + brow) * AAP + kc + bcol) * 4;
                uint32_t r0, r1, r2, r3;
                ldsm4(r0, r1, r2, r3, addr);
                bfr[nf2 * 2][0] = r0; bfr[nf2 * 2][1] = r1;
                bfr[nf2 * 2 + 1][0] = r2; bfr[nf2 * 2 + 1][1] = r3;
            }
            #pragma unroll
            for (int nf = 0; nf < 8; nf++)
                mma_tf32(o[nf], ap, bfr[nf]);
        }
    }

    // ---- epilogue: normalize, tf32-truncate (feeds mma_out), store ----
    float inv0 = 1.0f / l_0;
    float inv1 = 1.0f / l_1;
    int r0g = q0 + w * 16 + g;
    int r1g = r0g + 8;
    #pragma unroll
    for (int nf = 0; nf < 8; nf++) {
        int col = n * HD + nf * 8 + tq * 2;
        *(float2*)&g_Ctx[((size_t)(b * L_ + r0g)) * D_ + col] =
            make_float2(cvt_tf32f(o[nf][0] * inv0), cvt_tf32f(o[nf][1] * inv0));
        *(float2*)&g_Ctx[((size_t)(b * L_ + r1g)) * D_ + col] =
            make_float2(cvt_tf32f(o[nf][2] * inv1), cvt_tf32f(o[nf][3] * inv1));
    }
}

// ---------------------------------------------------------------------------
// Inputs: 0=q 1=k 2=v 3=mask 4=Wq 5=bq 6=Wk 7=bk 8=Wv 9=bv 10=Wo 11=bo
// ---------------------------------------------------------------------------
extern "C" void kernel_launch(void* const* d_in, const int* in_sizes, int n_in,
                              void* d_out, int out_size) {
    const float* q  = (const float*)d_in[0];
    const float* k  = (const float*)d_in[1];
    const float* v  = (const float*)d_in[2];
    const unsigned int* mask = (const unsigned int*)d_in[3];
    const float* Wq = (const float*)d_in[4];
    const float* bq = (const float*)d_in[5];
    const float* Wk = (const float*)d_in[6];
    const float* bk = (const float*)d_in[7];
    const float* Wv = (const float*)d_in[8];
    const float* bv = (const float*)d_in[9];
    const float* Wo = (const float*)d_in[10];
    const float* bo = (const float*)d_in[11];
    float* out = (float*)d_out;

    cudaFuncSetAttribute(attn_mma_kernel, cudaFuncAttributeMaxDynamicSharedMemorySize, ATT_SMEM);
    cudaFuncSetAttribute(mma_qkv_kernel, cudaFuncAttributeMaxDynamicSharedMemorySize, GEMM_SMEM);
    cudaFuncSetAttribute(mma_out_kernel, cudaFuncAttributeMaxDynamicSharedMemorySize, GEMM_SMEM);

    float *d_qT, *d_kT, *d_vT, *d_WT;
    cudaGetSymbolAddress((void**)&d_qT, g_qT);
    cudaGetSymbolAddress((void**)&d_kT, g_kT);
    cudaGetSymbolAddress((void**)&d_vT, g_vT);
    cudaGetSymbolAddress((void**)&d_WT, g_WT);

    rope_table_kernel<<<(L_ * (HD / 2) + 255) / 256, 256>>>();

    // tf32 prepass (rna) — inputs and weights
    const int XN4 = M_ * D_ / 4;          // 1M float4
    const int WN4 = D_ * D_ / 4;          // 256K float4
    trunc_kernel<<<(XN4 + 255) / 256, 256>>>((const float4*)q, (float4*)d_qT, XN4);
    trunc_kernel<<<(XN4 + 255) / 256, 256>>>((const float4*)k, (float4*)d_kT, XN4);
    trunc_kernel<<<(XN4 + 255) / 256, 256>>>((const float4*)v, (float4*)d_vT, XN4);
    trunc_kernel<<<(WN4 + 255) / 256, 256>>>((const float4*)Wq, (float4*)(d_WT + 0 * D_ * D_), WN4);
    trunc_kernel<<<(WN4 + 255) / 256, 256>>>((const float4*)Wk, (float4*)(d_WT + 1 * (size_t)D_ * D_), WN4);
    trunc_kernel<<<(WN4 + 255) / 256, 256>>>((const float4*)Wv, (float4*)(d_WT + 2 * (size_t)D_ * D_), WN4);
    trunc_kernel<<<(WN4 + 255) / 256, 256>>>((const float4*)Wo, (float4*)(d_WT + 3 * (size_t)D_ * D_), WN4);

    mma_qkv_kernel<<<dim3(D_ / 128, M_ / 128, 3), 256, GEMM_SMEM>>>(bq, bk, bv);
    attn_mma_kernel<<<dim3(L_ / 64, B_ * NH), 128, ATT_SMEM>>>(mask);
    mma_out_kernel<<<dim3(D_ / 128, M_ / 128), 256, GEMM_SMEM>>>(bo, out);
}

// round 13
// speedup vs baseline: 1.1777x; 1.1777x over previous
#include <cuda_runtime.h>
#include <cstdint>
#include <math.h>

// Problem constants
constexpr int B_  = 2;
constexpr int L_  = 2048;
constexpr int D_  = 1024;
constexpr int NH  = 16;
constexpr int HD  = 64;
constexpr int M_  = B_ * L_;     // 4096 rows for projections

// Scratch (device globals; no allocation allowed)
__device__ float  g_Qp[B_ * NH * L_ * HD];   // (b, n, l, h) roped, tf32-truncated
__device__ float  g_Kp[B_ * NH * L_ * HD];   // (b, n, l, h) roped, tf32-truncated
__device__ float  g_Vp[B_ * NH * L_ * HD];   // (b, n, hd, token) TRANSPOSED, tf32-truncated
__device__ float  g_Ctx[B_ * L_ * D_];       // attention output, tf32-truncated
__device__ float2 g_rope[L_ * (HD / 2)];     // (cos, sin) per (l, i)
__device__ float  g_WT[4 * D_ * D_];         // tf32-truncated Wq, Wk, Wv, Wo

// ---------------------------------------------------------------------------
// PTX helpers
// ---------------------------------------------------------------------------
__device__ __forceinline__ uint32_t smem_u32(const void* p) {
    uint32_t a;
    asm("{ .reg .u64 t; cvta.to.shared.u64 t, %1; cvt.u32.u64 %0, t; }" : "=r"(a) : "l"(p));
    return a;
}

__device__ __forceinline__ void cp_async16(uint32_t saddr, const void* gaddr) {
    asm volatile("cp.async.cg.shared.global [%0], [%1], 16;" :: "r"(saddr), "l"(gaddr) : "memory");
}
__device__ __forceinline__ void cp_commit() {
    asm volatile("cp.async.commit_group;" ::: "memory");
}
template<int N> __device__ __forceinline__ void cp_wait() {
    asm volatile("cp.async.wait_group %0;" :: "n"(N) : "memory");
}

__device__ __forceinline__ void ldsm4(uint32_t& r0, uint32_t& r1, uint32_t& r2, uint32_t& r3,
                                      uint32_t addr) {
    asm volatile("ldmatrix.sync.aligned.m8n8.x4.shared.b16 {%0,%1,%2,%3}, [%4];"
                 : "=r"(r0), "=r"(r1), "=r"(r2), "=r"(r3) : "r"(addr));
}

__device__ __forceinline__ void cvt_tf32(uint32_t& r) {
    asm("cvt.rna.tf32.f32 %0, %0;" : "+r"(r));
}
__device__ __forceinline__ float cvt_tf32f(float x) {
    uint32_t r = __float_as_uint(x);
    asm("cvt.rna.tf32.f32 %0, %0;" : "+r"(r));
    return __uint_as_float(r);
}

__device__ __forceinline__ void mma_tf32(float* c, const uint32_t* a, const uint32_t* b) {
    asm volatile(
        "mma.sync.aligned.m16n8k8.row.col.f32.tf32.tf32.f32 "
        "{%0,%1,%2,%3}, {%4,%5,%6,%7}, {%8,%9}, {%0,%1,%2,%3};"
        : "+f"(c[0]), "+f"(c[1]), "+f"(c[2]), "+f"(c[3])
        : "r"(a[0]), "r"(a[1]), "r"(a[2]), "r"(a[3]), "r"(b[0]), "r"(b[1]));
}

// ---------------------------------------------------------------------------
// Weight prepass: rna-truncate to tf32 (weights only — small & amortized)
// ---------------------------------------------------------------------------
__global__ void trunc_kernel(const float4* __restrict__ src, float4* __restrict__ dst, int n4) {
    int i = blockIdx.x * blockDim.x + threadIdx.x;
    if (i >= n4) return;
    float4 v = src[i];
    v.x = cvt_tf32f(v.x); v.y = cvt_tf32f(v.y);
    v.z = cvt_tf32f(v.z); v.w = cvt_tf32f(v.w);
    dst[i] = v;
}

// ---------------------------------------------------------------------------
// RoPE table
// ---------------------------------------------------------------------------
__global__ void rope_table_kernel() {
    int idx = blockIdx.x * blockDim.x + threadIdx.x;
    if (idx >= L_ * (HD / 2)) return;
    int l = idx >> 5;
    int i = idx & 31;
    float inv = powf(10000.0f, -(float)(2 * i) / 64.0f);
    float ang = (float)l * inv;
    float s, c;
    sincosf(ang, &s, &c);
    g_rope[idx] = make_float2(c, s);
}

// ---------------------------------------------------------------------------
// tf32 mma.sync GEMM core. CVT_A: rna-convert A-frags (raw fp32 inputs);
// B operand always comes from pre-truncated g_WT (or g_Ctx) — no cvt.
// ---------------------------------------------------------------------------
constexpr int P_ = 36;                          // smem pitch (floats)
constexpr int TILE_BYTES  = 128 * P_ * 4;       // 18432
constexpr int STAGE_BYTES = 2 * TILE_BYTES;     // X + W
constexpr int GEMM_SMEM   = 2 * STAGE_BYTES;    // 73728

template<bool CVT_A>
__device__ __forceinline__ void mma_proj_core(
    const float* __restrict__ X, const float* __restrict__ W,
    uint32_t sb, int m0, int n0, float acc[2][8][4])
{
    int tid = threadIdx.x;

    #pragma unroll
    for (int mf = 0; mf < 2; mf++)
        #pragma unroll
        for (int nf = 0; nf < 8; nf++)
            #pragma unroll
            for (int r = 0; r < 4; r++) acc[mf][nf][r] = 0.0f;

    const int lrow = tid >> 3;
    const int lcol = (tid & 7) * 4;
    const float* Xg = X + (size_t)(m0 + lrow) * D_ + lcol;
    const float* Wg = W + (size_t)(n0 + lrow) * D_ + lcol;
    const uint32_t sX = sb + (lrow * P_ + lcol) * 4;
    const uint32_t sW = sX + TILE_BYTES;

    const int lane = tid & 31;
    const int wm = (tid >> 5) & 3;
    const int wn = tid >> 7;
    const int arow = lane & 15;
    const int acol = (lane >> 4) * 4;
    const int brow = lane & 7;
    const int bcol = ((lane >> 3) & 1) * 4;
    const int bhi  = (lane >> 4) * 8;

    #pragma unroll
    for (int i = 0; i < 4; i++) {
        cp_async16(sX + i * 32 * P_ * 4, Xg + (size_t)i * 32 * D_);
        cp_async16(sW + i * 32 * P_ * 4, Wg + (size_t)i * 32 * D_);
    }
    cp_commit();

    for (int it = 0; it < 32; it++) {
        int s = it & 1;
        if (it < 31) {
            uint32_t off = ((it + 1) & 1) * STAGE_BYTES;
            int k0 = (it + 1) * 32;
            #pragma unroll
            for (int i = 0; i < 4; i++) {
                cp_async16(sX + off + i * 32 * P_ * 4, Xg + k0 + (size_t)i * 32 * D_);
                cp_async16(sW + off + i * 32 * P_ * 4, Wg + k0 + (size_t)i * 32 * D_);
            }
            cp_commit();
            cp_wait<1>();
        } else {
            cp_wait<0>();
        }
        __syncthreads();

        uint32_t xb = sb + s * STAGE_BYTES;
        uint32_t wb = xb + TILE_BYTES;

        #pragma unroll
        for (int ks = 0; ks < 4; ks++) {
            int kc = ks * 8;
            uint32_t a[2][4];
            #pragma unroll
            for (int mf = 0; mf < 2; mf++) {
                uint32_t addr = xb + ((wm * 32 + mf * 16 + arow) * P_ + kc + acol) * 4;
                ldsm4(a[mf][0], a[mf][1], a[mf][2], a[mf][3], addr);
                if (CVT_A) {
                    cvt_tf32(a[mf][0]); cvt_tf32(a[mf][1]);
                    cvt_tf32(a[mf][2]); cvt_tf32(a[mf][3]);
                }
            }
            uint32_t b[8][2];
            #pragma unroll
            for (int nf2 = 0; nf2 < 4; nf2++) {
                uint32_t addr = wb + ((wn * 64 + nf2 * 16 + bhi + brow) * P_ + kc + bcol) * 4;
                uint32_t r0, r1, r2, r3;
                ldsm4(r0, r1, r2, r3, addr);
                b[nf2 * 2][0] = r0; b[nf2 * 2][1] = r1;
                b[nf2 * 2 + 1][0] = r2; b[nf2 * 2 + 1][1] = r3;
            }
            #pragma unroll
            for (int mf = 0; mf < 2; mf++)
                #pragma unroll
                for (int nf = 0; nf < 8; nf++)
                    mma_tf32(acc[mf][nf], a[mf], b[nf]);
        }
        __syncthreads();
    }
}

// ---------------------------------------------------------------------------
// QKV projection: bias + RoPE (z<2) + tf32-truncate + scatter.
// Q/K -> (b, n, l, h).  V -> TRANSPOSED (b, n, h, l) for attention cp.async.
// ---------------------------------------------------------------------------
__global__ __launch_bounds__(256, 2) void mma_qkv_kernel(
    const float* __restrict__ q, const float* __restrict__ k, const float* __restrict__ v,
    const float* __restrict__ bq, const float* __restrict__ bk, const float* __restrict__ bv)
{
    extern __shared__ float sm[];
    uint32_t sb = smem_u32(sm);

    int z = blockIdx.z;
    const float* X    = (z == 0) ? q  : (z == 1) ? k  : v;
    const float* W    = g_WT + (size_t)z * D_ * D_;
    const float* bias = (z == 0) ? bq : (z == 1) ? bk : bv;
    bool do_rope = (z < 2);

    int m0 = blockIdx.y * 128;
    int n0 = blockIdx.x * 128;

    float acc[2][8][4];
    mma_proj_core<true>(X, W, sb, m0, n0, acc);

    int tid = threadIdx.x;
    int lane = tid & 31;
    int wm = (tid >> 5) & 3;
    int wn = tid >> 7;
    int g = lane >> 2, tq = lane & 3;

    #pragma unroll
    for (int mf = 0; mf < 2; mf++) {
        #pragma unroll
        for (int rr = 0; rr < 2; rr++) {
            int m = m0 + wm * 32 + mf * 16 + g + rr * 8;
            int l = m & (L_ - 1);
            int bb = m >> 11;
            #pragma unroll
            for (int nf = 0; nf < 8; nf++) {
                int col = n0 + wn * 64 + nf * 8 + tq * 2;
                float2 b2 = *(const float2*)&bias[col];
                float c0 = acc[mf][nf][rr * 2 + 0] + b2.x;
                float c1 = acc[mf][nf][rr * 2 + 1] + b2.y;
                int h = col & 63;
                int n = col >> 6;
                if (do_rope) {
                    float2 cs = g_rope[(l << 5) + (h >> 1)];
                    float e = c0, o = c1;
                    c0 = e * cs.x - o * cs.y;
                    c1 = o * cs.x + e * cs.y;
                    float* dst = ((z == 0) ? g_Qp : g_Kp)
                               + (((size_t)(bb * NH + n)) * L_ + l) * HD + h;
                    *(float2*)dst = make_float2(cvt_tf32f(c0), cvt_tf32f(c1));
                } else {
                    // V: transposed per-head layout [hd][token]
                    float* dstV = g_Vp + ((size_t)(bb * NH + n)) * L_ * HD;
                    dstV[(size_t)h * L_ + l]       = cvt_tf32f(c0);
                    dstV[(size_t)(h + 1) * L_ + l] = cvt_tf32f(c1);
                }
            }
        }
    }
}

// ---------------------------------------------------------------------------
// Output projection: Y = g_Ctx @ Wo^T + bo (both operands pre-truncated)
// ---------------------------------------------------------------------------
__global__ __launch_bounds__(256, 2) void mma_out_kernel(
    const float* __restrict__ bo, float* __restrict__ Y)
{
    extern __shared__ float sm[];
    uint32_t sb = smem_u32(sm);

    int m0 = blockIdx.y * 128;
    int n0 = blockIdx.x * 128;

    float acc[2][8][4];
    mma_proj_core<false>(g_Ctx, g_WT + (size_t)3 * D_ * D_, sb, m0, n0, acc);

    int tid = threadIdx.x;
    int lane = tid & 31;
    int wm = (tid >> 5) & 3;
    int wn = tid >> 7;
    int g = lane >> 2, tq = lane & 3;

    #pragma unroll
    for (int mf = 0; mf < 2; mf++) {
        #pragma unroll
        for (int rr = 0; rr < 2; rr++) {
            int m = m0 + wm * 32 + mf * 16 + g + rr * 8;
            #pragma unroll
            for (int nf = 0; nf < 8; nf++) {
                int col = n0 + wn * 64 + nf * 8 + tq * 2;
                float2 b2 = *(const float2*)&bo[col];
                *(float2*)&Y[(size_t)m * D_ + col] =
                    make_float2(acc[mf][nf][rr * 2 + 0] + b2.x,
                                acc[mf][nf][rr * 2 + 1] + b2.y);
            }
        }
    }
}

// ---------------------------------------------------------------------------
// Flash attention, tf32 mma.sync + cp.async double-buffered K/Vt/mask tiles.
// Grid (L/64, B*NH), 128 threads = 4 warps; warp w owns q-rows w*16..+15.
// g_Vp is pre-transposed [hd][token] so Vt tiles are straight copies.
// ---------------------------------------------------------------------------
constexpr int AAP = 68;
constexpr int KT_BYTES = 64 * AAP * 4;                     // 17408 per tile buffer
constexpr int ATT_SMEM = 5 * KT_BYTES + 2 * 64 * 4;        // Ks[2], Vt[2], Ps, msk[2]
constexpr float SCALE_ = 0.03125f;                         // 1/sqrt(1024)

__global__ __launch_bounds__(128) void attn_mma_kernel(const unsigned int* __restrict__ maskw)
{
    extern __shared__ float smf[];
    float* Ks0 = smf;                       // [2][64][AAP]
    float* Vt0 = smf + 2 * 64 * AAP;        // [2][64][AAP]
    float* Ps  = smf + 4 * 64 * AAP;        // [64][AAP] (also Q staging)
    unsigned int* msk0 = (unsigned int*)(smf + 5 * 64 * AAP);  // [2][64]

    const uint32_t sKs = smem_u32(Ks0);
    const uint32_t sVt = smem_u32(Vt0);
    const uint32_t sPs = smem_u32(Ps);
    const uint32_t sMsk = smem_u32(msk0);

    int bh = blockIdx.y;
    int q0 = blockIdx.x * 64;
    int b  = bh >> 4;
    int n  = bh & 15;

    const float* Q = g_Qp + (size_t)bh * L_ * HD;
    const float* K = g_Kp + (size_t)bh * L_ * HD;
    const float* V = g_Vp + (size_t)bh * L_ * HD;   // [hd][token]

    int tid  = threadIdx.x;
    int lane = tid & 31;
    int w    = tid >> 5;
    int g    = lane >> 2, tq = lane & 3;
    int arow = lane & 15;
    int acol = (lane >> 4) * 4;
    int brow = lane & 7;
    int bcol = ((lane >> 3) & 1) * 4;
    int bhi  = (lane >> 4) * 8;

    // ---- prologue: prefetch tile 0 ----
    {
        uint32_t kb = sKs, vb = sVt;
        #pragma unroll
        for (int i = 0; i < 8; i++) {
            int idx = tid + i * 128;
            int r = idx >> 4, c4 = idx & 15;
            cp_async16(kb + (r * AAP + c4 * 4) * 4, K + (size_t)r * HD + c4 * 4);
            cp_async16(vb + (r * AAP + c4 * 4) * 4, V + (size_t)r * L_ + c4 * 4);
        }
        if (tid < 16) cp_async16(sMsk + tid * 16, maskw + b * L_ + tid * 4);
        cp_commit();
    }

    // ---- stage Q into Ps, preload A-frags (pre-truncated) ----
    #pragma unroll
    for (int idx = tid; idx < 64 * 16; idx += 128) {
        int r = idx >> 4, c4 = (idx & 15) * 4;
        *(float4*)&Ps[r * AAP + c4] = *(const float4*)&Q[(size_t)(q0 + r) * HD + c4];
    }
    __syncthreads();

    uint32_t aq[8][4];
    #pragma unroll
    for (int ks = 0; ks < 8; ks++) {
        uint32_t addr = sPs + ((w * 16 + arow) * AAP + ks * 8 + acol) * 4;
        ldsm4(aq[ks][0], aq[ks][1], aq[ks][2], aq[ks][3], addr);
    }
    __syncthreads();

    float m_0 = -INFINITY, m_1 = -INFINITY, l_0 = 0.0f, l_1 = 0.0f;
    float o[8][4];
    #pragma unroll
    for (int nf = 0; nf < 8; nf++)
        #pragma unroll
        for (int r = 0; r < 4; r++) o[nf][r] = 0.0f;

    for (int kt = 0; kt < L_ / 64; kt++) {
        int s = kt & 1;

        // prefetch next tile into the other buffer
        if (kt < L_ / 64 - 1) {
            int k0n = (kt + 1) * 64;
            int sn = s ^ 1;
            uint32_t kb = sKs + sn * KT_BYTES;
            uint32_t vb = sVt + sn * KT_BYTES;
            #pragma unroll
            for (int i = 0; i < 8; i++) {
                int idx = tid + i * 128;
                int r = idx >> 4, c4 = idx & 15;
                cp_async16(kb + (r * AAP + c4 * 4) * 4, K + (size_t)(k0n + r) * HD + c4 * 4);
                cp_async16(vb + (r * AAP + c4 * 4) * 4, V + (size_t)r * L_ + k0n + c4 * 4);
            }
            if (tid < 16) cp_async16(sMsk + sn * 256 + tid * 16, maskw + b * L_ + k0n + tid * 4);
            cp_commit();
            cp_wait<1>();
        } else {
            cp_wait<0>();
        }
        __syncthreads();

        uint32_t kb = sKs + s * KT_BYTES;
        uint32_t vb = sVt + s * KT_BYTES;
        const unsigned int* msk = msk0 + s * 64;

        // ---- S = Q @ K^T ----
        float sc[8][4];
        #pragma unroll
        for (int nf = 0; nf < 8; nf++)
            #pragma unroll
            for (int r = 0; r < 4; r++) sc[nf][r] = 0.0f;

        #pragma unroll
        for (int ks = 0; ks < 8; ks++) {
            int kc = ks * 8;
            uint32_t bfr[8][2];
            #pragma unroll
            for (int nf2 = 0; nf2 < 4; nf2++) {
                uint32_t addr = kb + ((nf2 * 16 + bhi + brow) * AAP + kc + bcol) * 4;
                uint32_t r0, r1, r2, r3;
                ldsm4(r0, r1, r2, r3, addr);
                bfr[nf2 * 2][0] = r0; bfr[nf2 * 2][1] = r1;
                bfr[nf2 * 2 + 1][0] = r2; bfr[nf2 * 2 + 1][1] = r3;
            }
            #pragma unroll
            for (int nf = 0; nf < 8; nf++)
                mma_tf32(sc[nf], aq[ks], bfr[nf]);
        }

        // ---- online softmax ----
        float mx0 = -INFINITY, mx1 = -INFINITY;
        #pragma unroll
        for (int nf = 0; nf < 8; nf++) {
            int c0 = nf * 8 + tq * 2;
            bool k0m = msk[c0] != 0;
            bool k1m = msk[c0 + 1] != 0;
            sc[nf][0] = k0m ? -1e8f : sc[nf][0] * SCALE_;
            sc[nf][1] = k1m ? -1e8f : sc[nf][1] * SCALE_;
            sc[nf][2] = k0m ? -1e8f : sc[nf][2] * SCALE_;
            sc[nf][3] = k1m ? -1e8f : sc[nf][3] * SCALE_;
            mx0 = fmaxf(mx0, fmaxf(sc[nf][0], sc[nf][1]));
            mx1 = fmaxf(mx1, fmaxf(sc[nf][2], sc[nf][3]));
        }
        mx0 = fmaxf(mx0, __shfl_xor_sync(0xffffffffu, mx0, 1));
        mx0 = fmaxf(mx0, __shfl_xor_sync(0xffffffffu, mx0, 2));
        mx1 = fmaxf(mx1, __shfl_xor_sync(0xffffffffu, mx1, 1));
        mx1 = fmaxf(mx1, __shfl_xor_sync(0xffffffffu, mx1, 2));

        float mn0 = fmaxf(m_0, mx0);
        float mn1 = fmaxf(m_1, mx1);
        float sc0 = __expf(m_0 - mn0);
        float sc1 = __expf(m_1 - mn1);

        float ll0 = 0.0f, ll1 = 0.0f;
        #pragma unroll
        for (int nf = 0; nf < 8; nf++) {
            float p0 = __expf(sc[nf][0] - mn0);
            float p1 = __expf(sc[nf][1] - mn0);
            float p2 = __expf(sc[nf][2] - mn1);
            float p3 = __expf(sc[nf][3] - mn1);
            ll0 += p0 + p1;
            ll1 += p2 + p3;
            int c0 = nf * 8 + tq * 2;
            *(float2*)&Ps[(w * 16 + g) * AAP + c0]     = make_float2(cvt_tf32f(p0), cvt_tf32f(p1));
            *(float2*)&Ps[(w * 16 + g + 8) * AAP + c0] = make_float2(cvt_tf32f(p2), cvt_tf32f(p3));
        }
        ll0 += __shfl_xor_sync(0xffffffffu, ll0, 1);
        ll0 += __shfl_xor_sync(0xffffffffu, ll0, 2);
        ll1 += __shfl_xor_sync(0xffffffffu, ll1, 1);
        ll1 += __shfl_xor_sync(0xffffffffu, ll1, 2);

        l_0 = l_0 * sc0 + ll0;
        l_1 = l_1 * sc1 + ll1;
        m_0 = mn0;
        m_1 = mn1;

        #pragma unroll
        for (int nf = 0; nf < 8; nf++) {
            o[nf][0] *= sc0; o[nf][1] *= sc0;
            o[nf][2] *= sc1; o[nf][3] *= sc1;
        }
        __syncwarp();     // Ps rows are warp-private

        // ---- O += P @ V ----
        #pragma unroll
        for (int ks = 0; ks < 8; ks++) {
            int kc = ks * 8;
            uint32_t ap[4];
            {
                uint32_t addr = sPs + ((w * 16 + arow) * AAP + kc + acol) * 4;
                ldsm4(ap[0], ap[1], ap[2], ap[3], addr);
            }
            uint32_t bfr[8][2];
            #pragma unroll
            for (int nf2 = 0; nf2 < 4; nf2++) {
                uint32_t addr = vb + ((nf2 * 16 + bhi + brow) * AAP + kc + bcol) * 4;
                uint32_t r0, r1, r2, r3;
                ldsm4(r0, r1, r2, r3, addr);
                bfr[nf2 * 2][0] = r0; bfr[nf2 * 2][1] = r1;
                bfr[nf2 * 2 + 1][0] = r2; bfr[nf2 * 2 + 1][1] = r3;
            }
            #pragma unroll
            for (int nf = 0; nf < 8; nf++)
                mma_tf32(o[nf], ap, bfr[nf]);
        }
        __syncthreads();   // all warps done with this buffer before next prefetch overwrites
    }

    // ---- epilogue: normalize, tf32-truncate (feeds mma_out), store ----
    float inv0 = 1.0f / l_0;
    float inv1 = 1.0f / l_1;
    int r0g = q0 + w * 16 + g;
    int r1g = r0g + 8;
    #pragma unroll
    for (int nf = 0; nf < 8; nf++) {
        int col = n * HD + nf * 8 + tq * 2;
        *(float2*)&g_Ctx[((size_t)(b * L_ + r0g)) * D_ + col] =
            make_float2(cvt_tf32f(o[nf][0] * inv0), cvt_tf32f(o[nf][1] * inv0));
        *(float2*)&g_Ctx[((size_t)(b * L_ + r1g)) * D_ + col] =
            make_float2(cvt_tf32f(o[nf][2] * inv1), cvt_tf32f(o[nf][3] * inv1));
    }
}

// ---------------------------------------------------------------------------
// Inputs: 0=q 1=k 2=v 3=mask 4=Wq 5=bq 6=Wk 7=bk 8=Wv 9=bv 10=Wo 11=bo
// ---------------------------------------------------------------------------
extern "C" void kernel_launch(void* const* d_in, const int* in_sizes, int n_in,
                              void* d_out, int out_size) {
    const float* q  = (const float*)d_in[0];
    const float* k  = (const float*)d_in[1];
    const float* v  = (const float*)d_in[2];
    const unsigned int* mask = (const unsigned int*)d_in[3];
    const float* Wq = (const float*)d_in[4];
    const float* bq = (const float*)d_in[5];
    const float* Wk = (const float*)d_in[6];
    const float* bk = (const float*)d_in[7];
    const float* Wv = (const float*)d_in[8];
    const float* bv = (const float*)d_in[9];
    const float* Wo = (const float*)d_in[10];
    const float* bo = (const float*)d_in[11];
    float* out = (float*)d_out;

    cudaFuncSetAttribute(attn_mma_kernel, cudaFuncAttributeMaxDynamicSharedMemorySize, ATT_SMEM);
    cudaFuncSetAttribute(mma_qkv_kernel, cudaFuncAttributeMaxDynamicSharedMemorySize, GEMM_SMEM);
    cudaFuncSetAttribute(mma_out_kernel, cudaFuncAttributeMaxDynamicSharedMemorySize, GEMM_SMEM);

    float* d_WT;
    cudaGetSymbolAddress((void**)&d_WT, g_WT);

    rope_table_kernel<<<(L_ * (HD / 2) + 255) / 256, 256>>>();

    // weights-only tf32 prepass (small; lets B-operand + mma_out skip cvt)
    const int WN4 = D_ * D_ / 4;
    trunc_kernel<<<(WN4 + 255) / 256, 256>>>((const float4*)Wq, (float4*)(d_WT + 0 * (size_t)D_ * D_), WN4);
    trunc_kernel<<<(WN4 + 255) / 256, 256>>>((const float4*)Wk, (float4*)(d_WT + 1 * (size_t)D_ * D_), WN4);
    trunc_kernel<<<(WN4 + 255) / 256, 256>>>((const float4*)Wv, (float4*)(d_WT + 2 * (size_t)D_ * D_), WN4);
    trunc_kernel<<<(WN4 + 255) / 256, 256>>>((const float4*)Wo, (float4*)(d_WT + 3 * (size_t)D_ * D_), WN4);

    mma_qkv_kernel<<<dim3(D_ / 128, M_ / 128, 3), 256, GEMM_SMEM>>>(q, k, v, bq, bk, bv);
    attn_mma_kernel<<<dim3(L_ / 64, B_ * NH), 128, ATT_SMEM>>>(mask);
    mma_out_kernel<<<dim3(D_ / 128, M_ / 128), 256, GEMM_SMEM>>>(bo, out);
}

// round 14
// speedup vs baseline: 1.2730x; 1.0810x over previous
#include <cuda_runtime.h>
#include <cstdint>
#include <math.h>

// Problem constants
constexpr int B_  = 2;
constexpr int L_  = 2048;
constexpr int D_  = 1024;
constexpr int NH  = 16;
constexpr int HD  = 64;
constexpr int M_  = B_ * L_;     // 4096 rows for projections

// Scratch (device globals; no allocation allowed)
__device__ float  g_Qp[B_ * NH * L_ * HD];   // (b, n, l, h) roped, tf32-truncated
__device__ float  g_Kp[B_ * NH * L_ * HD];   // (b, n, l, h) roped, tf32-truncated
__device__ float  g_Vp[B_ * NH * L_ * HD];   // (b, n, hd, token) TRANSPOSED, tf32-truncated
__device__ float  g_Ctx[B_ * L_ * D_];       // attention output, tf32-truncated
__device__ float2 g_rope[L_ * (HD / 2)];     // (cos, sin) per (l, i)
__device__ float  g_WT[4 * D_ * D_];         // tf32-truncated Wq, Wk, Wv, Wo

// ---------------------------------------------------------------------------
// PTX helpers
// ---------------------------------------------------------------------------
__device__ __forceinline__ uint32_t smem_u32(const void* p) {
    uint32_t a;
    asm("{ .reg .u64 t; cvta.to.shared.u64 t, %1; cvt.u32.u64 %0, t; }" : "=r"(a) : "l"(p));
    return a;
}

__device__ __forceinline__ void cp_async16(uint32_t saddr, const void* gaddr) {
    asm volatile("cp.async.cg.shared.global [%0], [%1], 16;" :: "r"(saddr), "l"(gaddr) : "memory");
}
__device__ __forceinline__ void cp_commit() {
    asm volatile("cp.async.commit_group;" ::: "memory");
}
template<int N> __device__ __forceinline__ void cp_wait() {
    asm volatile("cp.async.wait_group %0;" :: "n"(N) : "memory");
}

__device__ __forceinline__ void ldsm4(uint32_t& r0, uint32_t& r1, uint32_t& r2, uint32_t& r3,
                                      uint32_t addr) {
    asm volatile("ldmatrix.sync.aligned.m8n8.x4.shared.b16 {%0,%1,%2,%3}, [%4];"
                 : "=r"(r0), "=r"(r1), "=r"(r2), "=r"(r3) : "r"(addr));
}

__device__ __forceinline__ void cvt_tf32(uint32_t& r) {
    asm("cvt.rna.tf32.f32 %0, %0;" : "+r"(r));
}
__device__ __forceinline__ float cvt_tf32f(float x) {
    uint32_t r = __float_as_uint(x);
    asm("cvt.rna.tf32.f32 %0, %0;" : "+r"(r));
    return __uint_as_float(r);
}

__device__ __forceinline__ void mma_tf32(float* c, const uint32_t* a, const uint32_t* b) {
    asm volatile(
        "mma.sync.aligned.m16n8k8.row.col.f32.tf32.tf32.f32 "
        "{%0,%1,%2,%3}, {%4,%5,%6,%7}, {%8,%9}, {%0,%1,%2,%3};"
        : "+f"(c[0]), "+f"(c[1]), "+f"(c[2]), "+f"(c[3])
        : "r"(a[0]), "r"(a[1]), "r"(a[2]), "r"(a[3]), "r"(b[0]), "r"(b[1]));
}

// ---------------------------------------------------------------------------
// Weight prepass: rna-truncate all 4 weight matrices (single launch, grid.z)
// ---------------------------------------------------------------------------
__global__ void trunc_w_kernel(const float4* __restrict__ w0, const float4* __restrict__ w1,
                               const float4* __restrict__ w2, const float4* __restrict__ w3,
                               float4* __restrict__ dst, int n4) {
    int i = blockIdx.x * blockDim.x + threadIdx.x;
    if (i >= n4) return;
    int z = blockIdx.z;
    const float4* src = (z == 0) ? w0 : (z == 1) ? w1 : (z == 2) ? w2 : w3;
    float4 v = src[i];
    v.x = cvt_tf32f(v.x); v.y = cvt_tf32f(v.y);
    v.z = cvt_tf32f(v.z); v.w = cvt_tf32f(v.w);
    dst[(size_t)z * n4 + i] = v;
}

// ---------------------------------------------------------------------------
// RoPE table
// ---------------------------------------------------------------------------
__global__ void rope_table_kernel() {
    int idx = blockIdx.x * blockDim.x + threadIdx.x;
    if (idx >= L_ * (HD / 2)) return;
    int l = idx >> 5;
    int i = idx & 31;
    float inv = powf(10000.0f, -(float)(2 * i) / 64.0f);
    float ang = (float)l * inv;
    float s, c;
    sincosf(ang, &s, &c);
    g_rope[idx] = make_float2(c, s);
}

// ---------------------------------------------------------------------------
// tf32 mma.sync GEMM core. CVT_A: rna-convert A-frags (raw fp32 inputs);
// B operand always comes from pre-truncated g_WT (or g_Ctx) — no cvt.
// ---------------------------------------------------------------------------
constexpr int P_ = 36;                          // smem pitch (floats)
constexpr int TILE_BYTES  = 128 * P_ * 4;       // 18432
constexpr int STAGE_BYTES = 2 * TILE_BYTES;     // X + W
constexpr int GEMM_SMEM   = 2 * STAGE_BYTES;    // 73728

template<bool CVT_A>
__device__ __forceinline__ void mma_proj_core(
    const float* __restrict__ X, const float* __restrict__ W,
    uint32_t sb, int m0, int n0, float acc[2][8][4])
{
    int tid = threadIdx.x;

    #pragma unroll
    for (int mf = 0; mf < 2; mf++)
        #pragma unroll
        for (int nf = 0; nf < 8; nf++)
            #pragma unroll
            for (int r = 0; r < 4; r++) acc[mf][nf][r] = 0.0f;

    const int lrow = tid >> 3;
    const int lcol = (tid & 7) * 4;
    const float* Xg = X + (size_t)(m0 + lrow) * D_ + lcol;
    const float* Wg = W + (size_t)(n0 + lrow) * D_ + lcol;
    const uint32_t sX = sb + (lrow * P_ + lcol) * 4;
    const uint32_t sW = sX + TILE_BYTES;

    const int lane = tid & 31;
    const int wm = (tid >> 5) & 3;
    const int wn = tid >> 7;
    const int arow = lane & 15;
    const int acol = (lane >> 4) * 4;
    const int brow = lane & 7;
    const int bcol = ((lane >> 3) & 1) * 4;
    const int bhi  = (lane >> 4) * 8;

    #pragma unroll
    for (int i = 0; i < 4; i++) {
        cp_async16(sX + i * 32 * P_ * 4, Xg + (size_t)i * 32 * D_);
        cp_async16(sW + i * 32 * P_ * 4, Wg + (size_t)i * 32 * D_);
    }
    cp_commit();

    for (int it = 0; it < 32; it++) {
        int s = it & 1;
        if (it < 31) {
            uint32_t off = ((it + 1) & 1) * STAGE_BYTES;
            int k0 = (it + 1) * 32;
            #pragma unroll
            for (int i = 0; i < 4; i++) {
                cp_async16(sX + off + i * 32 * P_ * 4, Xg + k0 + (size_t)i * 32 * D_);
                cp_async16(sW + off + i * 32 * P_ * 4, Wg + k0 + (size_t)i * 32 * D_);
            }
            cp_commit();
            cp_wait<1>();
        } else {
            cp_wait<0>();
        }
        __syncthreads();

        uint32_t xb = sb + s * STAGE_BYTES;
        uint32_t wb = xb + TILE_BYTES;

        #pragma unroll
        for (int ks = 0; ks < 4; ks++) {
            int kc = ks * 8;
            uint32_t a[2][4];
            #pragma unroll
            for (int mf = 0; mf < 2; mf++) {
                uint32_t addr = xb + ((wm * 32 + mf * 16 + arow) * P_ + kc + acol) * 4;
                ldsm4(a[mf][0], a[mf][1], a[mf][2], a[mf][3], addr);
                if (CVT_A) {
                    cvt_tf32(a[mf][0]); cvt_tf32(a[mf][1]);
                    cvt_tf32(a[mf][2]); cvt_tf32(a[mf][3]);
                }
            }
            uint32_t b[8][2];
            #pragma unroll
            for (int nf2 = 0; nf2 < 4; nf2++) {
                uint32_t addr = wb + ((wn * 64 + nf2 * 16 + bhi + brow) * P_ + kc + bcol) * 4;
                uint32_t r0, r1, r2, r3;
                ldsm4(r0, r1, r2, r3, addr);
                b[nf2 * 2][0] = r0; b[nf2 * 2][1] = r1;
                b[nf2 * 2 + 1][0] = r2; b[nf2 * 2 + 1][1] = r3;
            }
            #pragma unroll
            for (int mf = 0; mf < 2; mf++)
                #pragma unroll
                for (int nf = 0; nf < 8; nf++)
                    mma_tf32(acc[mf][nf], a[mf], b[nf]);
        }
        __syncthreads();
    }
}

// ---------------------------------------------------------------------------
// QKV projection: bias + RoPE (z<2) + tf32-truncate + scatter.
// Q/K -> (b, n, l, h).  V -> TRANSPOSED (b, n, h, l) for attention cp.async.
// ---------------------------------------------------------------------------
__global__ __launch_bounds__(256, 2) void mma_qkv_kernel(
    const float* __restrict__ q, const float* __restrict__ k, const float* __restrict__ v,
    const float* __restrict__ bq, const float* __restrict__ bk, const float* __restrict__ bv)
{
    extern __shared__ float sm[];
    uint32_t sb = smem_u32(sm);

    int z = blockIdx.z;
    const float* X    = (z == 0) ? q  : (z == 1) ? k  : v;
    const float* W    = g_WT + (size_t)z * D_ * D_;
    const float* bias = (z == 0) ? bq : (z == 1) ? bk : bv;
    bool do_rope = (z < 2);

    int m0 = blockIdx.y * 128;
    int n0 = blockIdx.x * 128;

    float acc[2][8][4];
    mma_proj_core<true>(X, W, sb, m0, n0, acc);

    int tid = threadIdx.x;
    int lane = tid & 31;
    int wm = (tid >> 5) & 3;
    int wn = tid >> 7;
    int g = lane >> 2, tq = lane & 3;

    #pragma unroll
    for (int mf = 0; mf < 2; mf++) {
        #pragma unroll
        for (int rr = 0; rr < 2; rr++) {
            int m = m0 + wm * 32 + mf * 16 + g + rr * 8;
            int l = m & (L_ - 1);
            int bb = m >> 11;
            #pragma unroll
            for (int nf = 0; nf < 8; nf++) {
                int col = n0 + wn * 64 + nf * 8 + tq * 2;
                float2 b2 = *(const float2*)&bias[col];
                float c0 = acc[mf][nf][rr * 2 + 0] + b2.x;
                float c1 = acc[mf][nf][rr * 2 + 1] + b2.y;
                int h = col & 63;
                int n = col >> 6;
                if (do_rope) {
                    float2 cs = g_rope[(l << 5) + (h >> 1)];
                    float e = c0, o = c1;
                    c0 = e * cs.x - o * cs.y;
                    c1 = o * cs.x + e * cs.y;
                    float* dst = ((z == 0) ? g_Qp : g_Kp)
                               + (((size_t)(bb * NH + n)) * L_ + l) * HD + h;
                    *(float2*)dst = make_float2(cvt_tf32f(c0), cvt_tf32f(c1));
                } else {
                    // V: transposed per-head layout [hd][token]
                    float* dstV = g_Vp + ((size_t)(bb * NH + n)) * L_ * HD;
                    dstV[(size_t)h * L_ + l]       = cvt_tf32f(c0);
                    dstV[(size_t)(h + 1) * L_ + l] = cvt_tf32f(c1);
                }
            }
        }
    }
}

// ---------------------------------------------------------------------------
// Output projection: Y = g_Ctx @ Wo^T + bo (both operands pre-truncated)
// ---------------------------------------------------------------------------
__global__ __launch_bounds__(256, 2) void mma_out_kernel(
    const float* __restrict__ bo, float* __restrict__ Y)
{
    extern __shared__ float sm[];
    uint32_t sb = smem_u32(sm);

    int m0 = blockIdx.y * 128;
    int n0 = blockIdx.x * 128;

    float acc[2][8][4];
    mma_proj_core<false>(g_Ctx, g_WT + (size_t)3 * D_ * D_, sb, m0, n0, acc);

    int tid = threadIdx.x;
    int lane = tid & 31;
    int wm = (tid >> 5) & 3;
    int wn = tid >> 7;
    int g = lane >> 2, tq = lane & 3;

    #pragma unroll
    for (int mf = 0; mf < 2; mf++) {
        #pragma unroll
        for (int rr = 0; rr < 2; rr++) {
            int m = m0 + wm * 32 + mf * 16 + g + rr * 8;
            #pragma unroll
            for (int nf = 0; nf < 8; nf++) {
                int col = n0 + wn * 64 + nf * 8 + tq * 2;
                float2 b2 = *(const float2*)&bo[col];
                *(float2*)&Y[(size_t)m * D_ + col] =
                    make_float2(acc[mf][nf][rr * 2 + 0] + b2.x,
                                acc[mf][nf][rr * 2 + 1] + b2.y);
            }
        }
    }
}

// ---------------------------------------------------------------------------
// Flash attention, tf32 mma.sync, BM=128 q-rows per CTA, 256 threads (8 warps,
// warp w owns q-rows w*16..+15). K/V tiles (64 tokens) cp.async double-buffered
// and amortized over 128 q-rows. g_Vp pre-transposed [hd][token].
// ---------------------------------------------------------------------------
constexpr int AAP = 68;
constexpr int KT_BYTES = 64 * AAP * 4;                     // 17408 per K/V buffer
constexpr int PS_BYTES = 128 * AAP * 4;                    // 34816
constexpr int ATT_SMEM = 4 * KT_BYTES + PS_BYTES + 2 * 64 * 4;  // 104960
constexpr float SCALE_ = 0.03125f;                         // 1/sqrt(1024)

__global__ __launch_bounds__(256, 2) void attn_mma_kernel(const unsigned int* __restrict__ maskw)
{
    extern __shared__ float smf[];
    float* Ks0 = smf;                       // [2][64][AAP]
    float* Vt0 = smf + 2 * 64 * AAP;        // [2][64][AAP]
    float* Ps  = smf + 4 * 64 * AAP;        // [128][AAP] (also Q staging)
    unsigned int* msk0 = (unsigned int*)(smf + 4 * 64 * AAP + 128 * AAP);  // [2][64]

    const uint32_t sKs = smem_u32(Ks0);
    const uint32_t sVt = smem_u32(Vt0);
    const uint32_t sPs = smem_u32(Ps);
    const uint32_t sMsk = smem_u32(msk0);

    int bh = blockIdx.y;
    int q0 = blockIdx.x * 128;
    int b  = bh >> 4;
    int n  = bh & 15;

    const float* Q = g_Qp + (size_t)bh * L_ * HD;
    const float* K = g_Kp + (size_t)bh * L_ * HD;
    const float* V = g_Vp + (size_t)bh * L_ * HD;   // [hd][token]

    int tid  = threadIdx.x;
    int lane = tid & 31;
    int w    = tid >> 5;              // warp 0..7
    int g    = lane >> 2, tq = lane & 3;
    int arow = lane & 15;
    int acol = (lane >> 4) * 4;
    int brow = lane & 7;
    int bcol = ((lane >> 3) & 1) * 4;
    int bhi  = (lane >> 4) * 8;

    // ---- prologue: prefetch tile 0 (K, Vt, mask) ----
    {
        #pragma unroll
        for (int i = 0; i < 4; i++) {
            int idx = tid + i * 256;
            int r = idx >> 4, c4 = idx & 15;
            cp_async16(sKs + (r * AAP + c4 * 4) * 4, K + (size_t)r * HD + c4 * 4);
            cp_async16(sVt + (r * AAP + c4 * 4) * 4, V + (size_t)r * L_ + c4 * 4);
        }
        if (tid < 16) cp_async16(sMsk + tid * 16, maskw + b * L_ + tid * 4);
        cp_commit();
    }

    // ---- stage Q (128x64) into Ps, preload A-frags ----
    #pragma unroll
    for (int i = 0; i < 8; i++) {
        int idx = tid + i * 256;
        int r = idx >> 4, c4 = (idx & 15) * 4;
        *(float4*)&Ps[r * AAP + c4] = *(const float4*)&Q[(size_t)(q0 + r) * HD + c4];
    }
    __syncthreads();

    uint32_t aq[8][4];
    #pragma unroll
    for (int ks = 0; ks < 8; ks++) {
        uint32_t addr = sPs + ((w * 16 + arow) * AAP + ks * 8 + acol) * 4;
        ldsm4(aq[ks][0], aq[ks][1], aq[ks][2], aq[ks][3], addr);
    }
    __syncthreads();

    float m_0 = -INFINITY, m_1 = -INFINITY, l_0 = 0.0f, l_1 = 0.0f;
    float o[8][4];
    #pragma unroll
    for (int nf = 0; nf < 8; nf++)
        #pragma unroll
        for (int r = 0; r < 4; r++) o[nf][r] = 0.0f;

    for (int kt = 0; kt < L_ / 64; kt++) {
        int s = kt & 1;

        // prefetch next tile into the other buffer
        if (kt < L_ / 64 - 1) {
            int k0n = (kt + 1) * 64;
            int sn = s ^ 1;
            uint32_t kb = sKs + sn * KT_BYTES;
            uint32_t vb = sVt + sn * KT_BYTES;
            #pragma unroll
            for (int i = 0; i < 4; i++) {
                int idx = tid + i * 256;
                int r = idx >> 4, c4 = idx & 15;
                cp_async16(kb + (r * AAP + c4 * 4) * 4, K + (size_t)(k0n + r) * HD + c4 * 4);
                cp_async16(vb + (r * AAP + c4 * 4) * 4, V + (size_t)r * L_ + k0n + c4 * 4);
            }
            if (tid < 16) cp_async16(sMsk + sn * 256 + tid * 16, maskw + b * L_ + k0n + tid * 4);
            cp_commit();
            cp_wait<1>();
        } else {
            cp_wait<0>();
        }
        __syncthreads();

        uint32_t kb = sKs + s * KT_BYTES;
        uint32_t vb = sVt + s * KT_BYTES;
        const unsigned int* msk = msk0 + s * 64;

        // ---- S = Q @ K^T ----
        float sc[8][4];
        #pragma unroll
        for (int nf = 0; nf < 8; nf++)
            #pragma unroll
            for (int r = 0; r < 4; r++) sc[nf][r] = 0.0f;

        #pragma unroll
        for (int ks = 0; ks < 8; ks++) {
            int kc = ks * 8;
            uint32_t bfr[8][2];
            #pragma unroll
            for (int nf2 = 0; nf2 < 4; nf2++) {
                uint32_t addr = kb + ((nf2 * 16 + bhi + brow) * AAP + kc + bcol) * 4;
                uint32_t r0, r1, r2, r3;
                ldsm4(r0, r1, r2, r3, addr);
                bfr[nf2 * 2][0] = r0; bfr[nf2 * 2][1] = r1;
                bfr[nf2 * 2 + 1][0] = r2; bfr[nf2 * 2 + 1][1] = r3;
            }
            #pragma unroll
            for (int nf = 0; nf < 8; nf++)
                mma_tf32(sc[nf], aq[ks], bfr[nf]);
        }

        // ---- online softmax ----
        float mx0 = -INFINITY, mx1 = -INFINITY;
        #pragma unroll
        for (int nf = 0; nf < 8; nf++) {
            int c0 = nf * 8 + tq * 2;
            bool k0m = msk[c0] != 0;
            bool k1m = msk[c0 + 1] != 0;
            sc[nf][0] = k0m ? -1e8f : sc[nf][0] * SCALE_;
            sc[nf][1] = k1m ? -1e8f : sc[nf][1] * SCALE_;
            sc[nf][2] = k0m ? -1e8f : sc[nf][2] * SCALE_;
            sc[nf][3] = k1m ? -1e8f : sc[nf][3] * SCALE_;
            mx0 = fmaxf(mx0, fmaxf(sc[nf][0], sc[nf][1]));
            mx1 = fmaxf(mx1, fmaxf(sc[nf][2], sc[nf][3]));
        }
        mx0 = fmaxf(mx0, __shfl_xor_sync(0xffffffffu, mx0, 1));
        mx0 = fmaxf(mx0, __shfl_xor_sync(0xffffffffu, mx0, 2));
        mx1 = fmaxf(mx1, __shfl_xor_sync(0xffffffffu, mx1, 1));
        mx1 = fmaxf(mx1, __shfl_xor_sync(0xffffffffu, mx1, 2));

        float mn0 = fmaxf(m_0, mx0);
        float mn1 = fmaxf(m_1, mx1);
        float sc0 = __expf(m_0 - mn0);
        float sc1 = __expf(m_1 - mn1);

        float ll0 = 0.0f, ll1 = 0.0f;
        #pragma unroll
        for (int nf = 0; nf < 8; nf++) {
            float p0 = __expf(sc[nf][0] - mn0);
            float p1 = __expf(sc[nf][1] - mn0);
            float p2 = __expf(sc[nf][2] - mn1);
            float p3 = __expf(sc[nf][3] - mn1);
            ll0 += p0 + p1;
            ll1 += p2 + p3;
            int c0 = nf * 8 + tq * 2;
            *(float2*)&Ps[(w * 16 + g) * AAP + c0]     = make_float2(cvt_tf32f(p0), cvt_tf32f(p1));
            *(float2*)&Ps[(w * 16 + g + 8) * AAP + c0] = make_float2(cvt_tf32f(p2), cvt_tf32f(p3));
        }
        ll0 += __shfl_xor_sync(0xffffffffu, ll0, 1);
        ll0 += __shfl_xor_sync(0xffffffffu, ll0, 2);
        ll1 += __shfl_xor_sync(0xffffffffu, ll1, 1);
        ll1 += __shfl_xor_sync(0xffffffffu, ll1, 2);

        l_0 = l_0 * sc0 + ll0;
        l_1 = l_1 * sc1 + ll1;
        m_0 = mn0;
        m_1 = mn1;

        #pragma unroll
        for (int nf = 0; nf < 8; nf++) {
            o[nf][0] *= sc0; o[nf][1] *= sc0;
            o[nf][2] *= sc1; o[nf][3] *= sc1;
        }
        __syncwarp();     // Ps rows are warp-private

        // ---- O += P @ V ----
        #pragma unroll
        for (int ks = 0; ks < 8; ks++) {
            int kc = ks * 8;
            uint32_t ap[4];
            {
                uint32_t addr = sPs + ((w * 16 + arow) * AAP + kc + acol) * 4;
                ldsm4(ap[0], ap[1], ap[2], ap[3], addr);
            }
            uint32_t bfr[8][2];
            #pragma unroll
            for (int nf2 = 0; nf2 < 4; nf2++) {
                uint32_t addr = vb + ((nf2 * 16 + bhi + brow) * AAP + kc + bcol) * 4;
                uint32_t r0, r1, r2, r3;
                ldsm4(r0, r1, r2, r3, addr);
                bfr[nf2 * 2][0] = r0; bfr[nf2 * 2][1] = r1;
                bfr[nf2 * 2 + 1][0] = r2; bfr[nf2 * 2 + 1][1] = r3;
            }
            #pragma unroll
            for (int nf = 0; nf < 8; nf++)
                mma_tf32(o[nf], ap, bfr[nf]);
        }
        __syncthreads();   // all warps done with this buffer before next prefetch
    }

    // ---- epilogue: normalize, tf32-truncate (feeds mma_out), store ----
    float inv0 = 1.0f / l_0;
    float inv1 = 1.0f / l_1;
    int r0g = q0 + w * 16 + g;
    int r1g = r0g + 8;
    #pragma unroll
    for (int nf = 0; nf < 8; nf++) {
        int col = n * HD + nf * 8 + tq * 2;
        *(float2*)&g_Ctx[((size_t)(b * L_ + r0g)) * D_ + col] =
            make_float2(cvt_tf32f(o[nf][0] * inv0), cvt_tf32f(o[nf][1] * inv0));
        *(float2*)&g_Ctx[((size_t)(b * L_ + r1g)) * D_ + col] =
            make_float2(cvt_tf32f(o[nf][2] * inv1), cvt_tf32f(o[nf][3] * inv1));
    }
}

// ---------------------------------------------------------------------------
// Inputs: 0=q 1=k 2=v 3=mask 4=Wq 5=bq 6=Wk 7=bk 8=Wv 9=bv 10=Wo 11=bo
// ---------------------------------------------------------------------------
extern "C" void kernel_launch(void* const* d_in, const int* in_sizes, int n_in,
                              void* d_out, int out_size) {
    const float* q  = (const float*)d_in[0];
    const float* k  = (const float*)d_in[1];
    const float* v  = (const float*)d_in[2];
    const unsigned int* mask = (const unsigned int*)d_in[3];
    const float* Wq = (const float*)d_in[4];
    const float* bq = (const float*)d_in[5];
    const float* Wk = (const float*)d_in[6];
    const float* bk = (const float*)d_in[7];
    const float* Wv = (const float*)d_in[8];
    const float* bv = (const float*)d_in[9];
    const float* Wo = (const float*)d_in[10];
    const float* bo = (const float*)d_in[11];
    float* out = (float*)d_out;

    cudaFuncSetAttribute(attn_mma_kernel, cudaFuncAttributeMaxDynamicSharedMemorySize, ATT_SMEM);
    cudaFuncSetAttribute(mma_qkv_kernel, cudaFuncAttributeMaxDynamicSharedMemorySize, GEMM_SMEM);
    cudaFuncSetAttribute(mma_out_kernel, cudaFuncAttributeMaxDynamicSharedMemorySize, GEMM_SMEM);

    float* d_WT;
    cudaGetSymbolAddress((void**)&d_WT, g_WT);

    rope_table_kernel<<<(L_ * (HD / 2) + 255) / 256, 256>>>();

    // weights tf32 prepass — single launch, grid.z selects matrix
    const int WN4 = D_ * D_ / 4;
    trunc_w_kernel<<<dim3((WN4 + 255) / 256, 1, 4), 256>>>(
        (const float4*)Wq, (const float4*)Wk, (const float4*)Wv, (const float4*)Wo,
        (float4*)d_WT, WN4);

    mma_qkv_kernel<<<dim3(D_ / 128, M_ / 128, 3), 256, GEMM_SMEM>>>(q, k, v, bq, bk, bv);
    attn_mma_kernel<<<dim3(L_ / 128, B_ * NH), 256, ATT_SMEM>>>(mask);
    mma_out_kernel<<<dim3(D_ / 128, M_ / 128), 256, GEMM_SMEM>>>(bo, out);
}

// round 16
// speedup vs baseline: 1.2897x; 1.0131x over previous
#include <cuda_runtime.h>
#include <cstdint>
#include <math.h>

// Problem constants
constexpr int B_  = 2;
constexpr int L_  = 2048;
constexpr int D_  = 1024;
constexpr int NH  = 16;
constexpr int HD  = 64;
constexpr int M_  = B_ * L_;     // 4096 rows for projections

// Scratch (device globals; no allocation allowed)
__device__ float  g_Qp[B_ * NH * L_ * HD];   // (b, n, l, h) roped, tf32-truncated
__device__ float  g_Kp[B_ * NH * L_ * HD];   // (b, n, l, h) roped, tf32-truncated
__device__ float  g_Vp[B_ * NH * L_ * HD];   // (b, n, hd, token) TRANSPOSED, tf32-truncated
__device__ float  g_Ctx[B_ * L_ * D_];       // attention output, tf32-truncated
__device__ float2 g_rope[L_ * (HD / 2)];     // (cos, sin) per (l, i)
__device__ float  g_WT[4 * D_ * D_];         // tf32-truncated Wq, Wk, Wv, Wo
__device__ float  g_mbias[B_ * L_];          // 0 or -1e8*log2e (additive mask bias)

// ---------------------------------------------------------------------------
// PTX helpers
// ---------------------------------------------------------------------------
__device__ __forceinline__ uint32_t smem_u32(const void* p) {
    uint32_t a;
    asm("{ .reg .u64 t; cvta.to.shared.u64 t, %1; cvt.u32.u64 %0, t; }" : "=r"(a) : "l"(p));
    return a;
}

__device__ __forceinline__ void cp_async16(uint32_t saddr, const void* gaddr) {
    asm volatile("cp.async.cg.shared.global [%0], [%1], 16;" :: "r"(saddr), "l"(gaddr) : "memory");
}
__device__ __forceinline__ void cp_commit() {
    asm volatile("cp.async.commit_group;" ::: "memory");
}
template<int N> __device__ __forceinline__ void cp_wait() {
    asm volatile("cp.async.wait_group %0;" :: "n"(N) : "memory");
}

__device__ __forceinline__ void ldsm4(uint32_t& r0, uint32_t& r1, uint32_t& r2, uint32_t& r3,
                                      uint32_t addr) {
    asm volatile("ldmatrix.sync.aligned.m8n8.x4.shared.b16 {%0,%1,%2,%3}, [%4];"
                 : "=r"(r0), "=r"(r1), "=r"(r2), "=r"(r3) : "r"(addr));
}

__device__ __forceinline__ void cvt_tf32(uint32_t& r) {
    asm("cvt.rna.tf32.f32 %0, %0;" : "+r"(r));
}
__device__ __forceinline__ float cvt_tf32f(float x) {
    uint32_t r = __float_as_uint(x);
    asm("cvt.rna.tf32.f32 %0, %0;" : "+r"(r));
    return __uint_as_float(r);
}
__device__ __forceinline__ float ex2f(float x) {
    float y;
    asm("ex2.approx.f32 %0, %1;" : "=f"(y) : "f"(x));
    return y;
}

__device__ __forceinline__ void mma_tf32(float* c, const uint32_t* a, const uint32_t* b) {
    asm volatile(
        "mma.sync.aligned.m16n8k8.row.col.f32.tf32.tf32.f32 "
        "{%0,%1,%2,%3}, {%4,%5,%6,%7}, {%8,%9}, {%0,%1,%2,%3};"
        : "+f"(c[0]), "+f"(c[1]), "+f"(c[2]), "+f"(c[3])
        : "r"(a[0]), "r"(a[1]), "r"(a[2]), "r"(a[3]), "r"(b[0]), "r"(b[1]));
}

// ---------------------------------------------------------------------------
// Weight prepass: rna-truncate all 4 weight matrices (single launch, grid.z)
// ---------------------------------------------------------------------------
__global__ void trunc_w_kernel(const float4* __restrict__ w0, const float4* __restrict__ w1,
                               const float4* __restrict__ w2, const float4* __restrict__ w3,
                               float4* __restrict__ dst, int n4) {
    int i = blockIdx.x * blockDim.x + threadIdx.x;
    if (i >= n4) return;
    int z = blockIdx.z;
    const float4* src = (z == 0) ? w0 : (z == 1) ? w1 : (z == 2) ? w2 : w3;
    float4 v = src[i];
    v.x = cvt_tf32f(v.x); v.y = cvt_tf32f(v.y);
    v.z = cvt_tf32f(v.z); v.w = cvt_tf32f(v.w);
    dst[(size_t)z * n4 + i] = v;
}

// ---------------------------------------------------------------------------
// Mask -> additive base-2 bias (0 or -1e8*log2e)
// ---------------------------------------------------------------------------
__global__ void mask_bias_kernel(const unsigned int* __restrict__ m) {
    int i = blockIdx.x * blockDim.x + threadIdx.x;
    if (i < B_ * L_) g_mbias[i] = m[i] ? -1.44269504e8f : 0.0f;
}

// ---------------------------------------------------------------------------
// RoPE table
// ---------------------------------------------------------------------------
__global__ void rope_table_kernel() {
    int idx = blockIdx.x * blockDim.x + threadIdx.x;
    if (idx >= L_ * (HD / 2)) return;
    int l = idx >> 5;
    int i = idx & 31;
    float inv = powf(10000.0f, -(float)(2 * i) / 64.0f);
    float ang = (float)l * inv;
    float s, c;
    sincosf(ang, &s, &c);
    g_rope[idx] = make_float2(c, s);
}

// ---------------------------------------------------------------------------
// tf32 mma.sync GEMM core. CVT_A: rna-convert A-frags (raw fp32 inputs);
// B operand always comes from pre-truncated g_WT (or g_Ctx) — no cvt.
// ---------------------------------------------------------------------------
constexpr int P_ = 36;                          // smem pitch (floats)
constexpr int TILE_BYTES  = 128 * P_ * 4;       // 18432
constexpr int STAGE_BYTES = 2 * TILE_BYTES;     // X + W
constexpr int GEMM_SMEM   = 2 * STAGE_BYTES;    // 73728

template<bool CVT_A>
__device__ __forceinline__ void mma_proj_core(
    const float* __restrict__ X, const float* __restrict__ W,
    uint32_t sb, int m0, int n0, float acc[2][8][4])
{
    int tid = threadIdx.x;

    #pragma unroll
    for (int mf = 0; mf < 2; mf++)
        #pragma unroll
        for (int nf = 0; nf < 8; nf++)
            #pragma unroll
            for (int r = 0; r < 4; r++) acc[mf][nf][r] = 0.0f;

    const int lrow = tid >> 3;
    const int lcol = (tid & 7) * 4;
    const float* Xg = X + (size_t)(m0 + lrow) * D_ + lcol;
    const float* Wg = W + (size_t)(n0 + lrow) * D_ + lcol;
    const uint32_t sX = sb + (lrow * P_ + lcol) * 4;
    const uint32_t sW = sX + TILE_BYTES;

    const int lane = tid & 31;
    const int wm = (tid >> 5) & 3;
    const int wn = tid >> 7;
    const int arow = lane & 15;
    const int acol = (lane >> 4) * 4;
    const int brow = lane & 7;
    const int bcol = ((lane >> 3) & 1) * 4;
    const int bhi  = (lane >> 4) * 8;

    #pragma unroll
    for (int i = 0; i < 4; i++) {
        cp_async16(sX + i * 32 * P_ * 4, Xg + (size_t)i * 32 * D_);
        cp_async16(sW + i * 32 * P_ * 4, Wg + (size_t)i * 32 * D_);
    }
    cp_commit();

    for (int it = 0; it < 32; it++) {
        int s = it & 1;
        if (it < 31) {
            uint32_t off = ((it + 1) & 1) * STAGE_BYTES;
            int k0 = (it + 1) * 32;
            #pragma unroll
            for (int i = 0; i < 4; i++) {
                cp_async16(sX + off + i * 32 * P_ * 4, Xg + k0 + (size_t)i * 32 * D_);
                cp_async16(sW + off + i * 32 * P_ * 4, Wg + k0 + (size_t)i * 32 * D_);
            }
            cp_commit();
            cp_wait<1>();
        } else {
            cp_wait<0>();
        }
        __syncthreads();

        uint32_t xb = sb + s * STAGE_BYTES;
        uint32_t wb = xb + TILE_BYTES;

        #pragma unroll
        for (int ks = 0; ks < 4; ks++) {
            int kc = ks * 8;
            uint32_t a[2][4];
            #pragma unroll
            for (int mf = 0; mf < 2; mf++) {
                uint32_t addr = xb + ((wm * 32 + mf * 16 + arow) * P_ + kc + acol) * 4;
                ldsm4(a[mf][0], a[mf][1], a[mf][2], a[mf][3], addr);
                if (CVT_A) {
                    cvt_tf32(a[mf][0]); cvt_tf32(a[mf][1]);
                    cvt_tf32(a[mf][2]); cvt_tf32(a[mf][3]);
                }
            }
            uint32_t b[8][2];
            #pragma unroll
            for (int nf2 = 0; nf2 < 4; nf2++) {
                uint32_t addr = wb + ((wn * 64 + nf2 * 16 + bhi + brow) * P_ + kc + bcol) * 4;
                uint32_t r0, r1, r2, r3;
                ldsm4(r0, r1, r2, r3, addr);
                b[nf2 * 2][0] = r0; b[nf2 * 2][1] = r1;
                b[nf2 * 2 + 1][0] = r2; b[nf2 * 2 + 1][1] = r3;
            }
            #pragma unroll
            for (int mf = 0; mf < 2; mf++)
                #pragma unroll
                for (int nf = 0; nf < 8; nf++)
                    mma_tf32(acc[mf][nf], a[mf], b[nf]);
        }
        __syncthreads();
    }
}

// ---------------------------------------------------------------------------
// QKV projection: bias + RoPE (z<2) + tf32-truncate + scatter.
// Q/K -> (b, n, l, h).  V -> (b, n, h, l): staged through smem so global
// stores are float4-coalesced along the token dim (no write amplification).
// ---------------------------------------------------------------------------
__global__ __launch_bounds__(256, 2) void mma_qkv_kernel(
    const float* __restrict__ q, const float* __restrict__ k, const float* __restrict__ v,
    const float* __restrict__ bq, const float* __restrict__ bk, const float* __restrict__ bv)
{
    extern __shared__ float sm[];
    uint32_t sb = smem_u32(sm);

    int z = blockIdx.z;
    const float* X    = (z == 0) ? q  : (z == 1) ? k  : v;
    const float* W    = g_WT + (size_t)z * D_ * D_;
    const float* bias = (z == 0) ? bq : (z == 1) ? bk : bv;

    int m0 = blockIdx.y * 128;
    int n0 = blockIdx.x * 128;

    float acc[2][8][4];
    mma_proj_core<true>(X, W, sb, m0, n0, acc);

    int tid = threadIdx.x;
    int lane = tid & 31;
    int wm = (tid >> 5) & 3;
    int wn = tid >> 7;
    int g = lane >> 2, tq = lane & 3;

    if (z < 2) {
        #pragma unroll
        for (int mf = 0; mf < 2; mf++) {
            #pragma unroll
            for (int rr = 0; rr < 2; rr++) {
                int m = m0 + wm * 32 + mf * 16 + g + rr * 8;
                int l = m & (L_ - 1);
                int bb = m >> 11;
                #pragma unroll
                for (int nf = 0; nf < 8; nf++) {
                    int col = n0 + wn * 64 + nf * 8 + tq * 2;
                    float2 b2 = *(const float2*)&bias[col];
                    float c0 = acc[mf][nf][rr * 2 + 0] + b2.x;
                    float c1 = acc[mf][nf][rr * 2 + 1] + b2.y;
                    int h = col & 63;
                    int n = col >> 6;
                    float2 cs = g_rope[(l << 5) + (h >> 1)];
                    float e = c0, o = c1;
                    c0 = e * cs.x - o * cs.y;
                    c1 = o * cs.x + e * cs.y;
                    float* dst = ((z == 0) ? g_Qp : g_Kp)
                               + (((size_t)(bb * NH + n)) * L_ + l) * HD + h;
                    *(float2*)dst = make_float2(cvt_tf32f(c0), cvt_tf32f(c1));
                }
            }
        }
    } else {
        // V: stage transposed tile [col][row] in smem, then coalesced stores
        constexpr int VP = 132;                 // pitch (floats), 16B-aligned rows
        #pragma unroll
        for (int mf = 0; mf < 2; mf++) {
            #pragma unroll
            for (int rr = 0; rr < 2; rr++) {
                int lm = wm * 32 + mf * 16 + g + rr * 8;    // local token 0..127
                #pragma unroll
                for (int nf = 0; nf < 8; nf++) {
                    int lc = wn * 64 + nf * 8 + tq * 2;     // local out-col 0..127
                    float2 b2 = *(const float2*)&bias[n0 + lc];
                    sm[lc * VP + lm]       = cvt_tf32f(acc[mf][nf][rr * 2 + 0] + b2.x);
                    sm[(lc + 1) * VP + lm] = cvt_tf32f(acc[mf][nf][rr * 2 + 1] + b2.y);
                }
            }
        }
        __syncthreads();
        int l0 = m0 & (L_ - 1);
        int bb = m0 >> 11;
        #pragma unroll
        for (int i = tid; i < 128 * 32; i += 256) {
            int c  = i >> 5;            // out-col 0..127
            int l4 = (i & 31) << 2;     // token 0..124
            int col = n0 + c;
            int h = col & 63, nh = col >> 6;
            float4 vv = *(float4*)&sm[c * VP + l4];
            *(float4*)&g_Vp[((size_t)(bb * NH + nh)) * L_ * HD + (size_t)h * L_ + l0 + l4] = vv;
        }
    }
}

// ---------------------------------------------------------------------------
// Output projection: Y = g_Ctx @ Wo^T + bo (both operands pre-truncated)
// ---------------------------------------------------------------------------
__global__ __launch_bounds__(256, 2) void mma_out_kernel(
    const float* __restrict__ bo, float* __restrict__ Y)
{
    extern __shared__ float sm[];
    uint32_t sb = smem_u32(sm);

    int m0 = blockIdx.y * 128;
    int n0 = blockIdx.x * 128;

    float acc[2][8][4];
    mma_proj_core<false>(g_Ctx, g_WT + (size_t)3 * D_ * D_, sb, m0, n0, acc);

    int tid = threadIdx.x;
    int lane = tid & 31;
    int wm = (tid >> 5) & 3;
    int wn = tid >> 7;
    int g = lane >> 2, tq = lane & 3;

    #pragma unroll
    for (int mf = 0; mf < 2; mf++) {
        #pragma unroll
        for (int rr = 0; rr < 2; rr++) {
            int m = m0 + wm * 32 + mf * 16 + g + rr * 8;
            #pragma unroll
            for (int nf = 0; nf < 8; nf++) {
                int col = n0 + wn * 64 + nf * 8 + tq * 2;
                float2 b2 = *(const float2*)&bo[col];
                *(float2*)&Y[(size_t)m * D_ + col] =
                    make_float2(acc[mf][nf][rr * 2 + 0] + b2.x,
                                acc[mf][nf][rr * 2 + 1] + b2.y);
            }
        }
    }
}

// ---------------------------------------------------------------------------
// Flash attention, tf32 mma.sync, BM=128 q-rows, 256 threads (8 warps).
// Base-2 softmax with additive mask bias; P stored without cvt (HMMA
// truncates anyway). K/V tiles cp.async double-buffered; g_Vp pre-transposed.
// ---------------------------------------------------------------------------
constexpr int AAP = 68;
constexpr int KT_BYTES = 64 * AAP * 4;                     // 17408 per K/V buffer
constexpr int PS_BYTES = 128 * AAP * 4;                    // 34816
constexpr int ATT_SMEM = 4 * KT_BYTES + PS_BYTES + 2 * 64 * 4;  // 104960
constexpr float C2_ = 0.04508422003f;                      // (1/32) * log2(e)

__global__ __launch_bounds__(256, 2) void attn_mma_kernel()
{
    extern __shared__ float smf[];
    float* Ks0 = smf;                       // [2][64][AAP]
    float* Vt0 = smf + 2 * 64 * AAP;        // [2][64][AAP]
    float* Ps  = smf + 4 * 64 * AAP;        // [128][AAP] (also Q staging)
    float* mb0 = smf + 4 * 64 * AAP + 128 * AAP;  // [2][64] mask bias

    const uint32_t sKs = smem_u32(Ks0);
    const uint32_t sVt = smem_u32(Vt0);
    const uint32_t sPs = smem_u32(Ps);
    const uint32_t sMb = smem_u32(mb0);

    int bh = blockIdx.y;
    int q0 = blockIdx.x * 128;
    int b  = bh >> 4;
    int n  = bh & 15;

    const float* Q = g_Qp + (size_t)bh * L_ * HD;
    const float* K = g_Kp + (size_t)bh * L_ * HD;
    const float* V = g_Vp + (size_t)bh * L_ * HD;   // [hd][token]

    int tid  = threadIdx.x;
    int lane = tid & 31;
    int w    = tid >> 5;              // warp 0..7
    int g    = lane >> 2, tq = lane & 3;
    int arow = lane & 15;
    int acol = (lane >> 4) * 4;
    int brow = lane & 7;
    int bcol = ((lane >> 3) & 1) * 4;
    int bhi  = (lane >> 4) * 8;

    // ---- prologue: prefetch tile 0 (K, Vt, mask bias) ----
    {
        #pragma unroll
        for (int i = 0; i < 4; i++) {
            int idx = tid + i * 256;
            int r = idx >> 4, c4 = idx & 15;
            cp_async16(sKs + (r * AAP + c4 * 4) * 4, K + (size_t)r * HD + c4 * 4);
            cp_async16(sVt + (r * AAP + c4 * 4) * 4, V + (size_t)r * L_ + c4 * 4);
        }
        if (tid < 16) cp_async16(sMb + tid * 16, g_mbias + b * L_ + tid * 4);
        cp_commit();
    }

    // ---- stage Q (128x64) into Ps, preload A-frags ----
    #pragma unroll
    for (int i = 0; i < 8; i++) {
        int idx = tid + i * 256;
        int r = idx >> 4, c4 = (idx & 15) * 4;
        *(float4*)&Ps[r * AAP + c4] = *(const float4*)&Q[(size_t)(q0 + r) * HD + c4];
    }
    __syncthreads();

    uint32_t aq[8][4];
    #pragma unroll
    for (int ks = 0; ks < 8; ks++) {
        uint32_t addr = sPs + ((w * 16 + arow) * AAP + ks * 8 + acol) * 4;
        ldsm4(aq[ks][0], aq[ks][1], aq[ks][2], aq[ks][3], addr);
    }
    __syncthreads();

    float m_0 = -INFINITY, m_1 = -INFINITY, l_0 = 0.0f, l_1 = 0.0f;
    float o[8][4];
    #pragma unroll
    for (int nf = 0; nf < 8; nf++)
        #pragma unroll
        for (int r = 0; r < 4; r++) o[nf][r] = 0.0f;

    for (int kt = 0; kt < L_ / 64; kt++) {
        int s = kt & 1;

        // prefetch next tile into the other buffer
        if (kt < L_ / 64 - 1) {
            int k0n = (kt + 1) * 64;
            int sn = s ^ 1;
            uint32_t kb = sKs + sn * KT_BYTES;
            uint32_t vb = sVt + sn * KT_BYTES;
            #pragma unroll
            for (int i = 0; i < 4; i++) {
                int idx = tid + i * 256;
                int r = idx >> 4, c4 = idx & 15;
                cp_async16(kb + (r * AAP + c4 * 4) * 4, K + (size_t)(k0n + r) * HD + c4 * 4);
                cp_async16(vb + (r * AAP + c4 * 4) * 4, V + (size_t)r * L_ + k0n + c4 * 4);
            }
            if (tid < 16) cp_async16(sMb + sn * 256 + tid * 16, g_mbias + b * L_ + k0n + tid * 4);
            cp_commit();
            cp_wait<1>();
        } else {
            cp_wait<0>();
        }
        __syncthreads();

        uint32_t kb = sKs + s * KT_BYTES;
        uint32_t vb = sVt + s * KT_BYTES;
        const float* mb = mb0 + s * 64;

        // ---- S = Q @ K^T ----
        float sc[8][4];
        #pragma unroll
        for (int nf = 0; nf < 8; nf++)
            #pragma unroll
            for (int r = 0; r < 4; r++) sc[nf][r] = 0.0f;

        #pragma unroll
        for (int ks = 0; ks < 8; ks++) {
            int kc = ks * 8;
            uint32_t bfr[8][2];
            #pragma unroll
            for (int nf2 = 0; nf2 < 4; nf2++) {
                uint32_t addr = kb + ((nf2 * 16 + bhi + brow) * AAP + kc + bcol) * 4;
                uint32_t r0, r1, r2, r3;
                ldsm4(r0, r1, r2, r3, addr);
                bfr[nf2 * 2][0] = r0; bfr[nf2 * 2][1] = r1;
                bfr[nf2 * 2 + 1][0] = r2; bfr[nf2 * 2 + 1][1] = r3;
            }
            #pragma unroll
            for (int nf = 0; nf < 8; nf++)
                mma_tf32(sc[nf], aq[ks], bfr[nf]);
        }

        // ---- online softmax (base-2 domain, additive mask bias) ----
        float mx0 = -INFINITY, mx1 = -INFINITY;
        #pragma unroll
        for (int nf = 0; nf < 8; nf++) {
            int c0 = nf * 8 + tq * 2;
            float2 b2 = *(const float2*)&mb[c0];
            sc[nf][0] = fmaf(sc[nf][0], C2_, b2.x);
            sc[nf][1] = fmaf(sc[nf][1], C2_, b2.y);
            sc[nf][2] = fmaf(sc[nf][2], C2_, b2.x);
            sc[nf][3] = fmaf(sc[nf][3], C2_, b2.y);
            mx0 = fmaxf(mx0, fmaxf(sc[nf][0], sc[nf][1]));
            mx1 = fmaxf(mx1, fmaxf(sc[nf][2], sc[nf][3]));
        }
        mx0 = fmaxf(mx0, __shfl_xor_sync(0xffffffffu, mx0, 1));
        mx0 = fmaxf(mx0, __shfl_xor_sync(0xffffffffu, mx0, 2));
        mx1 = fmaxf(mx1, __shfl_xor_sync(0xffffffffu, mx1, 1));
        mx1 = fmaxf(mx1, __shfl_xor_sync(0xffffffffu, mx1, 2));

        float mn0 = fmaxf(m_0, mx0);
        float mn1 = fmaxf(m_1, mx1);
        float sc0 = ex2f(m_0 - mn0);
        float sc1 = ex2f(m_1 - mn1);

        float ll0 = 0.0f, ll1 = 0.0f;
        #pragma unroll
        for (int nf = 0; nf < 8; nf++) {
            float p0 = ex2f(sc[nf][0] - mn0);
            float p1 = ex2f(sc[nf][1] - mn0);
            float p2 = ex2f(sc[nf][2] - mn1);
            float p3 = ex2f(sc[nf][3] - mn1);
            ll0 += p0 + p1;
            ll1 += p2 + p3;
            int c0 = nf * 8 + tq * 2;
            *(float2*)&Ps[(w * 16 + g) * AAP + c0]     = make_float2(p0, p1);
            *(float2*)&Ps[(w * 16 + g + 8) * AAP + c0] = make_float2(p2, p3);
        }
        ll0 += __shfl_xor_sync(0xffffffffu, ll0, 1);
        ll0 += __shfl_xor_sync(0xffffffffu, ll0, 2);
        ll1 += __shfl_xor_sync(0xffffffffu, ll1, 1);
        ll1 += __shfl_xor_sync(0xffffffffu, ll1, 2);

        l_0 = l_0 * sc0 + ll0;
        l_1 = l_1 * sc1 + ll1;
        m_0 = mn0;
        m_1 = mn1;

        #pragma unroll
        for (int nf = 0; nf < 8; nf++) {
            o[nf][0] *= sc0; o[nf][1] *= sc0;
            o[nf][2] *= sc1; o[nf][3] *= sc1;
        }
        __syncwarp();     // Ps rows are warp-private

        // ---- O += P @ V ----
        #pragma unroll
        for (int ks = 0; ks < 8; ks++) {
            int kc = ks * 8;
            uint32_t ap[4];
            {
                uint32_t addr = sPs + ((w * 16 + arow) * AAP + kc + acol) * 4;
                ldsm4(ap[0], ap[1], ap[2], ap[3], addr);
            }
            uint32_t bfr[8][2];
            #pragma unroll
            for (int nf2 = 0; nf2 < 4; nf2++) {
                uint32_t addr = vb + ((nf2 * 16 + bhi + brow) * AAP + kc + bcol) * 4;
                uint32_t r0, r1, r2, r3;
                ldsm4(r0, r1, r2, r3, addr);
                bfr[nf2 * 2][0] = r0; bfr[nf2 * 2][1] = r1;
                bfr[nf2 * 2 + 1][0] = r2; bfr[nf2 * 2 + 1][1] = r3;
            }
            #pragma unroll
            for (int nf = 0; nf < 8; nf++)
                mma_tf32(o[nf], ap, bfr[nf]);
        }
        __syncthreads();   // all warps done with this buffer before next prefetch
    }

    // ---- epilogue: normalize, tf32-truncate (feeds mma_out), store ----
    float inv0 = 1.0f / l_0;
    float inv1 = 1.0f / l_1;
    int r0g = q0 + w * 16 + g;
    int r1g = r0g + 8;
    #pragma unroll
    for (int nf = 0; nf < 8; nf++) {
        int col = n * HD + nf * 8 + tq * 2;
        *(float2*)&g_Ctx[((size_t)(b * L_ + r0g)) * D_ + col] =
            make_float2(cvt_tf32f(o[nf][0] * inv0), cvt_tf32f(o[nf][1] * inv0));
        *(float2*)&g_Ctx[((size_t)(b * L_ + r1g)) * D_ + col] =
            make_float2(cvt_tf32f(o[nf][2] * inv1), cvt_tf32f(o[nf][3] * inv1));
    }
}

// ---------------------------------------------------------------------------
// Inputs: 0=q 1=k 2=v 3=mask 4=Wq 5=bq 6=Wk 7=bk 8=Wv 9=bv 10=Wo 11=bo
// ---------------------------------------------------------------------------
extern "C" void kernel_launch(void* const* d_in, const int* in_sizes, int n_in,
                              void* d_out, int out_size) {
    const float* q  = (const float*)d_in[0];
    const float* k  = (const float*)d_in[1];
    const float* v  = (const float*)d_in[2];
    const unsigned int* mask = (const unsigned int*)d_in[3];
    const float* Wq = (const float*)d_in[4];
    const float* bq = (const float*)d_in[5];
    const float* Wk = (const float*)d_in[6];
    const float* bk = (const float*)d_in[7];
    const float* Wv = (const float*)d_in[8];
    const float* bv = (const float*)d_in[9];
    const float* Wo = (const float*)d_in[10];
    const float* bo = (const float*)d_in[11];
    float* out = (float*)d_out;

    cudaFuncSetAttribute(attn_mma_kernel, cudaFuncAttributeMaxDynamicSharedMemorySize, ATT_SMEM);
    cudaFuncSetAttribute(mma_qkv_kernel, cudaFuncAttributeMaxDynamicSharedMemorySize, GEMM_SMEM);
    cudaFuncSetAttribute(mma_out_kernel, cudaFuncAttributeMaxDynamicSharedMemorySize, GEMM_SMEM);

    float* d_WT;
    cudaGetSymbolAddress((void**)&d_WT, g_WT);

    rope_table_kernel<<<(L_ * (HD / 2) + 255) / 256, 256>>>();
    mask_bias_kernel<<<(B_ * L_ + 255) / 256, 256>>>(mask);

    const int WN4 = D_ * D_ / 4;
    trunc_w_kernel<<<dim3((WN4 + 255) / 256, 1, 4), 256>>>(
        (const float4*)Wq, (const float4*)Wk, (const float4*)Wv, (const float4*)Wo,
        (float4*)d_WT, WN4);

    mma_qkv_kernel<<<dim3(D_ / 128, M_ / 128, 3), 256, GEMM_SMEM>>>(q, k, v, bq, bk, bv);
    attn_mma_kernel<<<dim3(L_ / 128, B_ * NH), 256, ATT_SMEM>>>();
    mma_out_kernel<<<dim3(D_ / 128, M_ / 128), 256, GEMM_SMEM>>>(bo, out);
}